// round 11
// baseline (speedup 1.0000x reference)
#include <cuda_runtime.h>
#include <cstdint>

#define T_STEPS 64
typedef unsigned long long u64;

// ---------------- packed f32x2 helpers ----------------
__device__ __forceinline__ u64 ffma2(u64 a, u64 b, u64 c){
  u64 d; asm("fma.rn.f32x2 %0, %1, %2, %3;" : "=l"(d) : "l"(a), "l"(b), "l"(c)); return d;
}
__device__ __forceinline__ u64 addf2(u64 a, u64 b){
  u64 d; asm("add.rn.f32x2 %0, %1, %2;" : "=l"(d) : "l"(a), "l"(b)); return d;
}
__device__ __forceinline__ u64 pack2(float lo, float hi){
  u64 d; asm("mov.b64 %0, {%1, %2};" : "=l"(d) : "f"(lo), "f"(hi)); return d;
}
__device__ __forceinline__ float lo2(u64 a){ return __uint_as_float((unsigned)a); }
__device__ __forceinline__ float hi2(u64 a){ return __uint_as_float((unsigned)(a >> 32)); }
__device__ __forceinline__ float hsum2(u64 a){ return lo2(a) + hi2(a); }
__device__ __forceinline__ float rcpa(float x){
  float r; asm("rcp.approx.f32 %0, %1;" : "=f"(r) : "f"(x)); return r;
}

#define BAR_ELEM(e) asm volatile("bar.sync %0, 64;" :: "r"((e)+1) : "memory")
#define BAR_PAIR(p) asm volatile("bar.sync %0, 64;" :: "r"((p)+9) : "memory")

// ---------------- repacked weights (loop-invariant, built by pre-kernel) ----------------
__device__ __align__(16) float gatP[49152];   // [l][k4][c][4] : gatW[l][4k4+i][c]
__device__ __align__(16) float WihP[65536];   // [k4][c][4]
__device__ __align__(16) float WhhP[65536];
__device__ __align__(16) float pW1P[8192];
__device__ __align__(16) float aW1P[8192];
__device__ __align__(16) float aW2P[2048];
__device__ __align__(16) float bsumP[512];    // b_ih + b_hh

__global__ void repack_kernel(const float* __restrict__ gatW, const float* __restrict__ W_ih,
                              const float* __restrict__ W_hh, const float* __restrict__ pW1,
                              const float* __restrict__ aW1,  const float* __restrict__ aW2,
                              const float* __restrict__ b_ih, const float* __restrict__ b_hh){
  for (int idx = blockIdx.x*blockDim.x + threadIdx.x; idx < 199168; idx += gridDim.x*blockDim.x){
    if (idx < 49152){
      int f = idx; int i = f&3, c = (f>>2)&127, k4 = (f>>9)&31, l = f>>14;
      gatP[f] = gatW[(l*128 + k4*4 + i)*128 + c];
    } else if (idx < 114688){
      int f = idx - 49152; int i = f&3, c = (f>>2)&511, k4 = f>>11;
      WihP[f] = W_ih[(k4*4+i)*512 + c];
    } else if (idx < 180224){
      int f = idx - 114688; int i = f&3, c = (f>>2)&511, k4 = f>>11;
      WhhP[f] = W_hh[(k4*4+i)*512 + c];
    } else if (idx < 188416){
      int f = idx - 180224; int i = f&3, c = (f>>2)&63, k4 = f>>8;
      pW1P[f] = pW1[(k4*4+i)*64 + c];
    } else if (idx < 196608){
      int f = idx - 188416; int i = f&3, c = (f>>2)&63, k4 = f>>8;
      aW1P[f] = aW1[(k4*4+i)*64 + c];
    } else if (idx < 198656){
      int f = idx - 196608; int i = f&3, c = (f>>2)&31, k4 = f>>7;
      aW2P[f] = aW2[(k4*4+i)*32 + c];
    } else {
      int f = idx - 198656;
      bsumP[f] = b_ih[f] + b_hh[f];
    }
  }
}

// ---------------- threefry2x32 (exact JAX, partitionable path) ----------------
__device__ __forceinline__ uint32_t rotl32(uint32_t x, int d){ return __funnelshift_l(x, x, d); }

__device__ __forceinline__ void threefry(uint32_t k0, uint32_t k1, uint32_t x0, uint32_t x1,
                                         uint32_t& o0, uint32_t& o1){
  uint32_t k2 = k0 ^ k1 ^ 0x1BD11BDAu;
  x0 += k0; x1 += k1;
  #define TFR(a,b,c,d) \
    x0 += x1; x1 = rotl32(x1,a); x1 ^= x0; \
    x0 += x1; x1 = rotl32(x1,b); x1 ^= x0; \
    x0 += x1; x1 = rotl32(x1,c); x1 ^= x0; \
    x0 += x1; x1 = rotl32(x1,d); x1 ^= x0;
  TFR(13,15,26,6)  x0 += k1; x1 += k2 + 1u;
  TFR(17,29,16,24) x0 += k2; x1 += k0 + 2u;
  TFR(13,15,26,6)  x0 += k0; x1 += k1 + 3u;
  TFR(17,29,16,24) x0 += k1; x1 += k2 + 4u;
  TFR(13,15,26,6)  x0 += k2; x1 += k0 + 5u;
  #undef TFR
  o0 = x0; o1 = x1;
}

// XLA ErfInv f32 (Giles polynomial)
__device__ __forceinline__ float erfinv_f(float x){
  float w = -__logf(fmaf(-x, x, 1.0f));
  float p;
  if (w < 5.0f){
    w -= 2.5f;
    p = 2.81022636e-08f;
    p = fmaf(p, w, 3.43273939e-07f);
    p = fmaf(p, w, -3.5233877e-06f);
    p = fmaf(p, w, -4.39150654e-06f);
    p = fmaf(p, w, 0.00021858087f);
    p = fmaf(p, w, -0.00125372503f);
    p = fmaf(p, w, -0.00417768164f);
    p = fmaf(p, w, 0.246640727f);
    p = fmaf(p, w, 1.50140941f);
  } else {
    w = sqrtf(w) - 3.0f;
    p = -0.000200214257f;
    p = fmaf(p, w, 0.000100950558f);
    p = fmaf(p, w, 0.00134934322f);
    p = fmaf(p, w, -0.00367342844f);
    p = fmaf(p, w, 0.00573950773f);
    p = fmaf(p, w, -0.0076224613f);
    p = fmaf(p, w, 0.00943887047f);
    p = fmaf(p, w, 1.00167406f);
    p = fmaf(p, w, 2.83297682f);
  }
  return p * x;
}

__device__ __forceinline__ float bits_to_normal(uint32_t bits){
  float f = __uint_as_float((bits >> 9) | 0x3f800000u) - 1.0f;
  const float lo = -0.99999994f;
  float u = fmaf(f, 2.0f, lo);
  u = fmaxf(u, lo);
  return 1.41421356237309515f * erfinv_f(u);
}

__device__ __forceinline__ float warpsum(float v){
  #pragma unroll
  for (int o = 16; o > 0; o >>= 1) v += __shfl_xor_sync(0xffffffffu, v, o);
  return v;
}
__device__ __forceinline__ u64 warpsum2(u64 v){
  #pragma unroll
  for (int o = 16; o > 0; o >>= 1){
    uint32_t l = (uint32_t)v, h = (uint32_t)(v >> 32);
    l = __shfl_xor_sync(0xffffffffu, l, o);
    h = __shfl_xor_sync(0xffffffffu, h, o);
    v = addf2(v, ((u64)h << 32) | l);
  }
  return v;
}
__device__ __forceinline__ float sig_(float x){ return rcpa(1.0f + __expf(-x)); }
__device__ __forceinline__ float tanh_(float x){ return fmaf(2.0f, rcpa(1.0f + __expf(-2.0f*x)), -1.0f); }

// ------- mega kernel: 1 block = 8 elems, 512 thr, elem-batched GEMMs, 1 CTA/SM -------
__global__ __launch_bounds__(512, 1)
void vkc_kernel(
  const int*   __restrict__ gesture_idx,
  const float* __restrict__ demographics,
  const float* __restrict__ emb_table,
  const float* __restrict__ dW1, const float* __restrict__ db1,
  const float* __restrict__ dW2, const float* __restrict__ db2,
  const float* __restrict__ jiW, const float* __restrict__ jib,
  const float* __restrict__ gat_asrc,
  const float* __restrict__ gat_adst, const float* __restrict__ gat_b,
  const float* __restrict__ ln_g, const float* __restrict__ ln_b,
  const float* __restrict__ pb1,
  const float* __restrict__ pW2, const float* __restrict__ pb2,
  const float* __restrict__ ab1,
  const float* __restrict__ ab2,
  const float* __restrict__ aW3, const float* __restrict__ ab3,
  float* __restrict__ out)
{
  __shared__ __align__(16) float xs[24][128];   // x state: 8 elems x 3 joints
  __shared__ __align__(16) float UB[4096];      // union: xp rows / gates / combined, 512/elem
  __shared__ __align__(16) float hs[8][128];
  __shared__ __align__(16) float cs[8][128];
  __shared__ __align__(16) float scr[8][64];
  __shared__ __align__(16) float physs[8][4];

  const int tid  = threadIdx.x;
  const int w    = tid >> 5;     // warp 0..15
  const int lane = tid & 31;
  const int e    = w >> 1;       // local element 0..7
  const int wh   = w & 1;        // warp-half within element
  const int g    = blockIdx.x;   // 0..127
  const int b    = g*8 + e;
  const int wr   = e * 3;        // row base in xs
  const int col  = tid & 127;
  const int rg   = tid >> 7;     // rowgroup 0..3 (setup GEMM only)
  const int c0   = wh*32 + lane;
  float* const xpE = UB + e*512; // this elem's xp slot (rows r at +r*128)
  float* const gtE = UB + e*512; // this elem's gates slot

  // ---------------- setup: demo MLP + embedding -> combined ----------------
  {
    float dm[7];
    #pragma unroll
    for (int i = 0; i < 7; i++) dm[i] = demographics[b*7 + i];
    float a0 = db1[c0];
    #pragma unroll
    for (int i = 0; i < 7; i++) a0 = fmaf(dm[i], dW1[i*64 + c0], a0);
    scr[e][c0] = fmaxf(a0, 0.f);
  }
  __syncthreads();
  {
    const int gi = gesture_idx[b];
    #pragma unroll
    for (int q = 0; q < 2; q++){
      int c = wh*64 + 32*q + lane;
      gtE[c] = emb_table[gi*128 + c];
      float acc = db2[c];
      #pragma unroll 4
      for (int k = 0; k < 64; k++) acc = fmaf(scr[e][k], dW2[k*128 + c], acc);
      gtE[128 + c] = acc;
      hs[e][c] = 0.f; cs[e][c] = 0.f;
    }
  }
  __syncthreads();

  // ---------------- jf = relu(combined @ jiW + jib) -> xs ----------------
  {
    float acc[6];
    #pragma unroll
    for (int i = 0; i < 6; i++) acc[i] = 0.f;
    const int ebase = rg*2;
    #pragma unroll 4
    for (int k = 0; k < 256; k++){
      float w0 = jiW[0*32768 + k*128 + col];
      float w1 = jiW[1*32768 + k*128 + col];
      float w2 = jiW[2*32768 + k*128 + col];
      #pragma unroll
      for (int ee = 0; ee < 2; ee++){
        float cv = UB[(ebase + ee)*512 + k];
        acc[ee*3+0] = fmaf(cv, w0, acc[ee*3+0]);
        acc[ee*3+1] = fmaf(cv, w1, acc[ee*3+1]);
        acc[ee*3+2] = fmaf(cv, w2, acc[ee*3+2]);
      }
    }
    __syncthreads();     // UB (combined) consumed; reused as xp below
    #pragma unroll
    for (int ri = 0; ri < 6; ri++){
      int j = ri % 3;
      xs[rg*6 + ri][col] = fmaxf(acc[ri] + jib[j*128 + col], 0.f);
    }
  }
  __syncthreads();

  // ---------------- time loop ----------------
  for (int t = 0; t < T_STEPS; t++){
    // ===== 3 GAT layers =====
    #pragma unroll 1
    for (int l = 0; l < 3; l++){
      // GEMM (warps 0-3): warp wg -> elems {2wg, 2wg+1}, 4 cols/thread
      if (w < 4){
        const float* Wl = gatP + l*16384;
        const int r0 = (2*w)*3, r1 = (2*w+1)*3;
        float* xp0 = UB + (2*w)*512;
        float* xp1 = UB + (2*w+1)*512;
        u64 acc[4][6];
        #pragma unroll
        for (int j = 0; j < 4; j++)
          #pragma unroll
          for (int m = 0; m < 6; m++) acc[j][m] = 0ull;
        #pragma unroll 4
        for (int k4 = 0; k4 < 32; k4++){
          ulonglong2 xv[6];
          #pragma unroll
          for (int r = 0; r < 3; r++){
            xv[r]   = *reinterpret_cast<const ulonglong2*>(&xs[r0+r][k4*4]);
            xv[3+r] = *reinterpret_cast<const ulonglong2*>(&xs[r1+r][k4*4]);
          }
          #pragma unroll
          for (int j = 0; j < 4; j++){
            const ulonglong2 wv = *reinterpret_cast<const ulonglong2*>(Wl + (k4*128 + lane + 32*j)*4);
            #pragma unroll
            for (int m = 0; m < 6; m++){
              acc[j][m] = ffma2(xv[m].x, wv.x, acc[j][m]);
              acc[j][m] = ffma2(xv[m].y, wv.y, acc[j][m]);
            }
          }
        }
        #pragma unroll
        for (int j = 0; j < 4; j++){
          int c = lane + 32*j;
          #pragma unroll
          for (int r = 0; r < 3; r++){
            xp0[r*128 + c] = hsum2(acc[j][r]);
            xp1[r*128 + c] = hsum2(acc[j][3+r]);
          }
        }
      }
      __syncthreads();

      // attention: 2 heads per warp (all 16 warps)
      {
        const float* as = gat_asrc + l*128;
        const float* ad = gat_adst + l*128;
        #pragma unroll
        for (int hh = 0; hh < 2; hh++){
          int h = 2*wh + hh;
          int c = h*32 + lane;
          float x0v = xpE[0*128+c], x1v = xpE[1*128+c], x2v = xpE[2*128+c];
          float av = as[c], dv = ad[c];
          u64 S01 = warpsum2(pack2(x0v*av, x1v*av));
          u64 SD2 = warpsum2(pack2(x2v*av, x2v*dv));
          float d1 = warpsum(x1v*dv);
          float s0 = lo2(S01), s1 = hi2(S01), s2 = lo2(SD2), d2 = hi2(SD2);
          float e10 = d1+s0; e10 = e10 > 0.f ? e10 : 0.2f*e10;
          float e11 = d1+s1; e11 = e11 > 0.f ? e11 : 0.2f*e11;
          float e21 = d2+s1; e21 = e21 > 0.f ? e21 : 0.2f*e21;
          float e22 = d2+s2; e22 = e22 > 0.f ? e22 : 0.2f*e22;
          float m1 = fmaxf(e10, e11);
          float p10 = __expf(e10-m1), p11 = __expf(e11-m1);
          float i1 = rcpa(p10+p11);
          float m2 = fmaxf(e21, e22);
          float p21 = __expf(e21-m2), p22 = __expf(e22-m2);
          float i2 = rcpa(p21+p22);
          xpE[1*128+c] = (p10*x0v + p11*x1v)*i1;
          xpE[2*128+c] = (p21*x1v + p22*x2v)*i2;
        }
      }
      BAR_ELEM(e);

      // bias + single-pass layernorm + relu + residual; wh0 -> rows 0,2 ; wh1 -> row 1
      {
        #pragma unroll
        for (int jj = 0; jj < 2; jj++){
          if (wh == 1 && jj == 1) break;
          int j = (wh == 0) ? (jj == 0 ? 0 : 2) : 1;
          float v[4];
          float s = 0.f, ss = 0.f;
          #pragma unroll
          for (int q = 0; q < 4; q++){
            int c = lane + 32*q;
            v[q] = xpE[j*128 + c] + gat_b[l*128 + c];
            s += v[q];
            ss = fmaf(v[q], v[q], ss);
          }
          u64 red = warpsum2(pack2(s, ss));
          float mu  = lo2(red) * (1.f/128.f);
          float var = fmaf(-mu, mu, hi2(red) * (1.f/128.f));
          float inv = rsqrtf(var + 1e-5f);
          #pragma unroll
          for (int q = 0; q < 4; q++){
            int c = lane + 32*q;
            float y = (v[q]-mu)*inv*ln_g[l*128 + c] + ln_b[l*128 + c];
            xs[wr+j][c] = fmaxf(y, 0.f) + xs[wr+j][c];
          }
        }
      }
      __syncthreads();
    }

    // ===== LSTM gates GEMM (warps 0-7): thread -> 4 cols x 4 elems, weights read once =====
    if (w < 8){
      const int egrp = w >> 2;            // 0: elems 0-3, 1: elems 4-7
      const int ct = tid & 127;
      u64 acc[4][4];
      #pragma unroll
      for (int j = 0; j < 4; j++){
        const u64 binit = pack2(bsumP[ct + 128*j], 0.f);
        #pragma unroll
        for (int ee = 0; ee < 4; ee++) acc[j][ee] = binit;
      }
      #pragma unroll 2
      for (int k4 = 0; k4 < 32; k4++){
        ulonglong2 xv[4], hv[4];
        #pragma unroll
        for (int ee = 0; ee < 4; ee++){
          xv[ee] = *reinterpret_cast<const ulonglong2*>(&xs[(egrp*4+ee)*3+2][k4*4]);
          hv[ee] = *reinterpret_cast<const ulonglong2*>(&hs[egrp*4+ee][k4*4]);
        }
        #pragma unroll
        for (int j = 0; j < 4; j++){
          const int c = ct + 128*j;
          const ulonglong2 wi = *reinterpret_cast<const ulonglong2*>(WihP + (k4*512 + c)*4);
          const ulonglong2 wo = *reinterpret_cast<const ulonglong2*>(WhhP + (k4*512 + c)*4);
          #pragma unroll
          for (int ee = 0; ee < 4; ee++){
            u64 a = acc[j][ee];
            a = ffma2(xv[ee].x, wi.x, a); a = ffma2(xv[ee].y, wi.y, a);
            a = ffma2(hv[ee].x, wo.x, a); a = ffma2(hv[ee].y, wo.y, a);
            acc[j][ee] = a;
          }
        }
      }
      #pragma unroll
      for (int j = 0; j < 4; j++)
        #pragma unroll
        for (int ee = 0; ee < 4; ee++)
          UB[(egrp*4+ee)*512 + ct + 128*j] = hsum2(acc[j][ee]);
    }
    __syncthreads();

    // ===== LSTM pointwise (all warps; bias folded in) =====
    {
      #pragma unroll
      for (int qq = 0; qq < 2; qq++){
        int cx = lane + 32*(2*wh + qq);
        float gi = gtE[cx];
        float gf = gtE[128 + cx];
        float gg = gtE[256 + cx];
        float go = gtE[384 + cx];
        float cn = sig_(gf)*cs[e][cx] + sig_(gi)*tanh_(gg);
        float hn = sig_(go)*tanh_(cn);
        cs[e][cx] = cn; hs[e][cx] = hn;
      }
    }

    // ===== noise (elem-local): x += 0.05 * normal * (t/64); skip t=0 and t=63 =====
    if (t >= 1 && t < T_STEPS - 1){
      const float scale = 0.05f * (float)t * (1.0f/64.0f);
      uint32_t kt0, kt1;
      threefry(0u, 42u, 0u, (uint32_t)t, kt0, kt1);
      #pragma unroll 1
      for (int ii = wh*32 + lane; ii < 384; ii += 64){
        uint32_t m = (uint32_t)(b*384 + ii);
        uint32_t o0, o1;
        threefry(kt0, kt1, 0u, m, o0, o1);
        xs[wr + (ii >> 7)][ii & 127] += scale * bits_to_normal(o0 ^ o1);
      }
    }
    __syncthreads();   // hs ready for head warps; noised xs done

    // ===== output heads (warps 0-7): warp pair p handles elems {2p, 2p+1} =====
    if (w < 8){
      const int p  = w >> 1;
      const int e0 = 2*p, e1 = 2*p + 1;
      if ((w & 1) == 0){
        // phys path for both elems (pW1 read once per pair)
        u64 pa0=0ull, pb0=0ull, pa1=0ull, pb1v=0ull;
        #pragma unroll 4
        for (int k4 = 0; k4 < 32; k4++){
          const ulonglong2 wA = *reinterpret_cast<const ulonglong2*>(pW1P + (k4*64 + lane   )*4);
          const ulonglong2 wB = *reinterpret_cast<const ulonglong2*>(pW1P + (k4*64 + lane+32)*4);
          const ulonglong2 h0 = *reinterpret_cast<const ulonglong2*>(&hs[e0][k4*4]);
          const ulonglong2 h1 = *reinterpret_cast<const ulonglong2*>(&hs[e1][k4*4]);
          pa0  = ffma2(h0.x, wA.x, pa0 ); pa0  = ffma2(h0.y, wA.y, pa0 );
          pb0  = ffma2(h0.x, wB.x, pb0 ); pb0  = ffma2(h0.y, wB.y, pb0 );
          pa1  = ffma2(h1.x, wA.x, pa1 ); pa1  = ffma2(h1.y, wA.y, pa1 );
          pb1v = ffma2(h1.x, wB.x, pb1v); pb1v = ffma2(h1.y, wB.y, pb1v);
        }
        const float w20 = pW2[lane*3+0],      w21 = pW2[lane*3+1],      w22 = pW2[lane*3+2];
        const float w30 = pW2[(lane+32)*3+0], w31 = pW2[(lane+32)*3+1], w32 = pW2[(lane+32)*3+2];
        {
          float p_a = fmaxf(hsum2(pa0) + pb1[lane],    0.f);
          float p_b = fmaxf(hsum2(pb0) + pb1[lane+32], 0.f);
          u64 P01 = warpsum2(pack2(p_a*w20 + p_b*w30, p_a*w21 + p_b*w31));
          float ph2 = warpsum(p_a*w22 + p_b*w32);
          if (lane == 0){
            physs[e0][0] = lo2(P01) + pb2[0];
            physs[e0][1] = hi2(P01) + pb2[1];
            physs[e0][2] = ph2      + pb2[2];
          }
        }
        {
          float p_a = fmaxf(hsum2(pa1)  + pb1[lane],    0.f);
          float p_b = fmaxf(hsum2(pb1v) + pb1[lane+32], 0.f);
          u64 P01 = warpsum2(pack2(p_a*w20 + p_b*w30, p_a*w21 + p_b*w31));
          float ph2 = warpsum(p_a*w22 + p_b*w32);
          if (lane == 0){
            physs[e1][0] = lo2(P01) + pb2[0];
            physs[e1][1] = hi2(P01) + pb2[1];
            physs[e1][2] = ph2      + pb2[2];
          }
        }
        BAR_PAIR(p);
      } else {
        // act path for both elems (aW1/aW2 read once per pair)
        u64 aa0=0ull, ab0=0ull, aa1=0ull, ab1v=0ull;
        #pragma unroll 4
        for (int k4 = 0; k4 < 32; k4++){
          const ulonglong2 wA = *reinterpret_cast<const ulonglong2*>(aW1P + (k4*64 + lane   )*4);
          const ulonglong2 wB = *reinterpret_cast<const ulonglong2*>(aW1P + (k4*64 + lane+32)*4);
          const ulonglong2 h0 = *reinterpret_cast<const ulonglong2*>(&hs[e0][k4*4]);
          const ulonglong2 h1 = *reinterpret_cast<const ulonglong2*>(&hs[e1][k4*4]);
          aa0  = ffma2(h0.x, wA.x, aa0 ); aa0  = ffma2(h0.y, wA.y, aa0 );
          ab0  = ffma2(h0.x, wB.x, ab0 ); ab0  = ffma2(h0.y, wB.y, ab0 );
          aa1  = ffma2(h1.x, wA.x, aa1 ); aa1  = ffma2(h1.y, wA.y, aa1 );
          ab1v = ffma2(h1.x, wB.x, ab1v); ab1v = ffma2(h1.y, wB.y, ab1v);
        }
        scr[e0][lane]    = fmaxf(hsum2(aa0)  + ab1[lane],    0.f);
        scr[e0][lane+32] = fmaxf(hsum2(ab0)  + ab1[lane+32], 0.f);
        scr[e1][lane]    = fmaxf(hsum2(aa1)  + ab1[lane],    0.f);
        scr[e1][lane+32] = fmaxf(hsum2(ab1v) + ab1[lane+32], 0.f);
        __syncwarp();
        u64 t2a0 = 0ull, t2a1 = 0ull;
        #pragma unroll
        for (int k4 = 0; k4 < 16; k4++){
          const ulonglong2 wv = *reinterpret_cast<const ulonglong2*>(aW2P + (k4*32 + lane)*4);
          const ulonglong2 s0 = *reinterpret_cast<const ulonglong2*>(&scr[e0][k4*4]);
          const ulonglong2 s1 = *reinterpret_cast<const ulonglong2*>(&scr[e1][k4*4]);
          t2a0 = ffma2(s0.x, wv.x, t2a0); t2a0 = ffma2(s0.y, wv.y, t2a0);
          t2a1 = ffma2(s1.x, wv.x, t2a1); t2a1 = ffma2(s1.y, wv.y, t2a1);
        }
        float t2_0 = fmaxf(hsum2(t2a0) + ab2[lane], 0.f);
        float t2_1 = fmaxf(hsum2(t2a1) + ab2[lane], 0.f);
        BAR_PAIR(p);
        const float a30 = aW3[lane*3+0], a31 = aW3[lane*3+1], a32 = aW3[lane*3+2];
        {
          u64 A01 = warpsum2(pack2(t2_0*a30, t2_0*a31));
          float a2 = warpsum(t2_0*a32);
          if (lane < 3){
            float v = (lane == 0) ? (lo2(A01) + ab3[0] + 0.1f*physs[e0][0])
                    : (lane == 1) ? (hi2(A01) + ab3[1] + 0.1f*physs[e0][1])
                                  : (a2       + ab3[2] + 0.1f*physs[e0][2]);
            out[((g*8 + e0)*T_STEPS + t)*3 + lane] = v;
          }
        }
        {
          u64 A01 = warpsum2(pack2(t2_1*a30, t2_1*a31));
          float a2 = warpsum(t2_1*a32);
          if (lane < 3){
            float v = (lane == 0) ? (lo2(A01) + ab3[0] + 0.1f*physs[e1][0])
                    : (lane == 1) ? (hi2(A01) + ab3[1] + 0.1f*physs[e1][1])
                                  : (a2       + ab3[2] + 0.1f*physs[e1][2]);
            out[((g*8 + e1)*T_STEPS + t)*3 + lane] = v;
          }
        }
      }
    }
    __syncthreads();   // end of step: xs/hs/cs/UB stable for next iteration
  }
}

extern "C" void kernel_launch(void* const* d_in, const int* in_sizes, int n_in,
                              void* d_out, int out_size)
{
  const int off = (n_in >= 30) ? 1 : 0;
  const int*   gesture_idx  = (const int*)  d_in[0];
  const float* demographics = (const float*)d_in[1];
  const float* emb_table = (const float*)d_in[2 + off];
  const float* dW1  = (const float*)d_in[3 + off];
  const float* db1  = (const float*)d_in[4 + off];
  const float* dW2  = (const float*)d_in[5 + off];
  const float* db2  = (const float*)d_in[6 + off];
  const float* jiW  = (const float*)d_in[7 + off];
  const float* jib  = (const float*)d_in[8 + off];
  const float* gatW = (const float*)d_in[9 + off];
  const float* gat_asrc = (const float*)d_in[10 + off];
  const float* gat_adst = (const float*)d_in[11 + off];
  const float* gat_b    = (const float*)d_in[12 + off];
  const float* ln_g = (const float*)d_in[13 + off];
  const float* ln_b = (const float*)d_in[14 + off];
  const float* W_ih = (const float*)d_in[15 + off];
  const float* W_hh = (const float*)d_in[16 + off];
  const float* b_ih = (const float*)d_in[17 + off];
  const float* b_hh = (const float*)d_in[18 + off];
  const float* pW1  = (const float*)d_in[19 + off];
  const float* pb1  = (const float*)d_in[20 + off];
  const float* pW2  = (const float*)d_in[21 + off];
  const float* pb2  = (const float*)d_in[22 + off];
  const float* aW1  = (const float*)d_in[23 + off];
  const float* ab1  = (const float*)d_in[24 + off];
  const float* aW2  = (const float*)d_in[25 + off];
  const float* ab2  = (const float*)d_in[26 + off];
  const float* aW3  = (const float*)d_in[27 + off];
  const float* ab3  = (const float*)d_in[28 + off];

  repack_kernel<<<128, 256>>>(gatW, W_ih, W_hh, pW1, aW1, aW2, b_ih, b_hh);
  vkc_kernel<<<128, 512>>>(gesture_idx, demographics, emb_table,
                           dW1, db1, dW2, db2, jiW, jib,
                           gat_asrc, gat_adst, gat_b, ln_g, ln_b,
                           pb1, pW2, pb2,
                           ab1, ab2,
                           aW3, ab3,
                           (float*)d_out);
}

// round 12
// speedup vs baseline: 1.2637x; 1.2637x over previous
#include <cuda_runtime.h>
#include <cstdint>

#define T_STEPS 64
typedef unsigned long long u64;

// ---------------- packed f32x2 helpers ----------------
__device__ __forceinline__ u64 ffma2(u64 a, u64 b, u64 c){
  u64 d; asm("fma.rn.f32x2 %0, %1, %2, %3;" : "=l"(d) : "l"(a), "l"(b), "l"(c)); return d;
}
__device__ __forceinline__ u64 addf2(u64 a, u64 b){
  u64 d; asm("add.rn.f32x2 %0, %1, %2;" : "=l"(d) : "l"(a), "l"(b)); return d;
}
__device__ __forceinline__ u64 pack2(float lo, float hi){
  u64 d; asm("mov.b64 %0, {%1, %2};" : "=l"(d) : "f"(lo), "f"(hi)); return d;
}
__device__ __forceinline__ float lo2(u64 a){ return __uint_as_float((unsigned)a); }
__device__ __forceinline__ float hi2(u64 a){ return __uint_as_float((unsigned)(a >> 32)); }
__device__ __forceinline__ float hsum2(u64 a){ return lo2(a) + hi2(a); }
__device__ __forceinline__ float rcpa(float x){
  float r; asm("rcp.approx.f32 %0, %1;" : "=f"(r) : "f"(x)); return r;
}

#define BAR_ELEM(e) asm volatile("bar.sync %0, 64;" :: "r"((e)+1) : "memory")

// ---------------- cp.async staging: 8192 floats (32KB) per call ----------------
__device__ __forceinline__ void stage8k(float* dst, const float* src, int tid){
  uint32_t s = (uint32_t)__cvta_generic_to_shared(dst) + tid*16;
  const char* gp = (const char*)src + tid*16;
  #pragma unroll
  for (int i = 0; i < 4; i++){
    asm volatile("cp.async.cg.shared.global [%0], [%1], 16;"
                 :: "r"(s + i*8192u), "l"(gp + i*8192) : "memory");
  }
}
__device__ __forceinline__ void cp_commit(){ asm volatile("cp.async.commit_group;" ::: "memory"); }
__device__ __forceinline__ void cp_wait_all(){ asm volatile("cp.async.wait_group 0;" ::: "memory"); }

// ---------------- repacked weights (loop-invariant, built by pre-kernel) ----------------
__device__ __align__(16) float gatP[49152];   // [l][k4][c][4]
__device__ __align__(16) float WihP[65536];   // [k4][c][4]
__device__ __align__(16) float WhhP[65536];
__device__ __align__(16) float headP[16384];  // [0:8192)=pW1 ; [8192:)=aW1
__device__ __align__(16) float aW2P[2048];
__device__ __align__(16) float bsumP[512];    // b_ih + b_hh

__global__ void repack_kernel(const float* __restrict__ gatW, const float* __restrict__ W_ih,
                              const float* __restrict__ W_hh, const float* __restrict__ pW1,
                              const float* __restrict__ aW1,  const float* __restrict__ aW2,
                              const float* __restrict__ b_ih, const float* __restrict__ b_hh){
  for (int idx = blockIdx.x*blockDim.x + threadIdx.x; idx < 199168; idx += gridDim.x*blockDim.x){
    if (idx < 49152){
      int f = idx; int i = f&3, c = (f>>2)&127, k4 = (f>>9)&31, l = f>>14;
      gatP[f] = gatW[(l*128 + k4*4 + i)*128 + c];
    } else if (idx < 114688){
      int f = idx - 49152; int i = f&3, c = (f>>2)&511, k4 = f>>11;
      WihP[f] = W_ih[(k4*4+i)*512 + c];
    } else if (idx < 180224){
      int f = idx - 114688; int i = f&3, c = (f>>2)&511, k4 = f>>11;
      WhhP[f] = W_hh[(k4*4+i)*512 + c];
    } else if (idx < 188416){
      int f = idx - 180224; int i = f&3, c = (f>>2)&63, k4 = f>>8;
      headP[f] = pW1[(k4*4+i)*64 + c];
    } else if (idx < 196608){
      int f = idx - 188416; int i = f&3, c = (f>>2)&63, k4 = f>>8;
      headP[8192 + f] = aW1[(k4*4+i)*64 + c];
    } else if (idx < 198656){
      int f = idx - 196608; int i = f&3, c = (f>>2)&31, k4 = f>>7;
      aW2P[f] = aW2[(k4*4+i)*32 + c];
    } else {
      int f = idx - 198656;
      bsumP[f] = b_ih[f] + b_hh[f];
    }
  }
}

// ---------------- threefry2x32 (exact JAX, partitionable path) ----------------
__device__ __forceinline__ uint32_t rotl32(uint32_t x, int d){ return __funnelshift_l(x, x, d); }

__device__ __forceinline__ void threefry(uint32_t k0, uint32_t k1, uint32_t x0, uint32_t x1,
                                         uint32_t& o0, uint32_t& o1){
  uint32_t k2 = k0 ^ k1 ^ 0x1BD11BDAu;
  x0 += k0; x1 += k1;
  #define TFR(a,b,c,d) \
    x0 += x1; x1 = rotl32(x1,a); x1 ^= x0; \
    x0 += x1; x1 = rotl32(x1,b); x1 ^= x0; \
    x0 += x1; x1 = rotl32(x1,c); x1 ^= x0; \
    x0 += x1; x1 = rotl32(x1,d); x1 ^= x0;
  TFR(13,15,26,6)  x0 += k1; x1 += k2 + 1u;
  TFR(17,29,16,24) x0 += k2; x1 += k0 + 2u;
  TFR(13,15,26,6)  x0 += k0; x1 += k1 + 3u;
  TFR(17,29,16,24) x0 += k1; x1 += k2 + 4u;
  TFR(13,15,26,6)  x0 += k2; x1 += k0 + 5u;
  #undef TFR
  o0 = x0; o1 = x1;
}

// XLA ErfInv f32 (Giles polynomial)
__device__ __forceinline__ float erfinv_f(float x){
  float w = -__logf(fmaf(-x, x, 1.0f));
  float p;
  if (w < 5.0f){
    w -= 2.5f;
    p = 2.81022636e-08f;
    p = fmaf(p, w, 3.43273939e-07f);
    p = fmaf(p, w, -3.5233877e-06f);
    p = fmaf(p, w, -4.39150654e-06f);
    p = fmaf(p, w, 0.00021858087f);
    p = fmaf(p, w, -0.00125372503f);
    p = fmaf(p, w, -0.00417768164f);
    p = fmaf(p, w, 0.246640727f);
    p = fmaf(p, w, 1.50140941f);
  } else {
    w = sqrtf(w) - 3.0f;
    p = -0.000200214257f;
    p = fmaf(p, w, 0.000100950558f);
    p = fmaf(p, w, 0.00134934322f);
    p = fmaf(p, w, -0.00367342844f);
    p = fmaf(p, w, 0.00573950773f);
    p = fmaf(p, w, -0.0076224613f);
    p = fmaf(p, w, 0.00943887047f);
    p = fmaf(p, w, 1.00167406f);
    p = fmaf(p, w, 2.83297682f);
  }
  return p * x;
}

__device__ __forceinline__ float bits_to_normal(uint32_t bits){
  float f = __uint_as_float((bits >> 9) | 0x3f800000u) - 1.0f;
  const float lo = -0.99999994f;
  float u = fmaf(f, 2.0f, lo);
  u = fmaxf(u, lo);
  return 1.41421356237309515f * erfinv_f(u);
}

__device__ __forceinline__ float warpsum(float v){
  #pragma unroll
  for (int o = 16; o > 0; o >>= 1) v += __shfl_xor_sync(0xffffffffu, v, o);
  return v;
}
__device__ __forceinline__ u64 warpsum2(u64 v){
  #pragma unroll
  for (int o = 16; o > 0; o >>= 1){
    uint32_t l = (uint32_t)v, h = (uint32_t)(v >> 32);
    l = __shfl_xor_sync(0xffffffffu, l, o);
    h = __shfl_xor_sync(0xffffffffu, h, o);
    v = addf2(v, ((u64)h << 32) | l);
  }
  return v;
}
__device__ __forceinline__ float sig_(float x){ return rcpa(1.0f + __expf(-x)); }
__device__ __forceinline__ float tanh_(float x){ return fmaf(2.0f, rcpa(1.0f + __expf(-2.0f*x)), -1.0f); }

// smem float offsets
#define SM_XS    0          // [24][128]
#define SM_UB    3072       // [8][512] union: xp rows / gates / combined
#define SM_HS    7168       // [8][128]
#define SM_CS    8192       // [8][128]
#define SM_SCR   9216       // [8][64]
#define SM_PHYS  9728       // [8][4]
#define SM_WS0   9760       // [16384] staging buffer 0 (64KB)
#define SM_WS1   26144      // [16384] staging buffer 1 (64KB)
#define SM_TOTAL_FLOATS 42528

// ------- mega kernel: 1 block = 8 elems, 2 warps/elem, staged weights, 1 CTA/SM -------
__global__ __launch_bounds__(512, 1)
void vkc_kernel(
  const int*   __restrict__ gesture_idx,
  const float* __restrict__ demographics,
  const float* __restrict__ emb_table,
  const float* __restrict__ dW1, const float* __restrict__ db1,
  const float* __restrict__ dW2, const float* __restrict__ db2,
  const float* __restrict__ jiW, const float* __restrict__ jib,
  const float* __restrict__ gat_asrc,
  const float* __restrict__ gat_adst, const float* __restrict__ gat_b,
  const float* __restrict__ ln_g, const float* __restrict__ ln_b,
  const float* __restrict__ pb1,
  const float* __restrict__ pW2, const float* __restrict__ pb2,
  const float* __restrict__ ab1,
  const float* __restrict__ ab2,
  const float* __restrict__ aW3, const float* __restrict__ ab3,
  float* __restrict__ out)
{
  extern __shared__ __align__(16) float sm[];
  float* const xs   = sm + SM_XS;
  float* const UB   = sm + SM_UB;
  float* const hs   = sm + SM_HS;
  float* const cs   = sm + SM_CS;
  float* const scr  = sm + SM_SCR;
  float* const phB  = sm + SM_PHYS;
  float* const WS0  = sm + SM_WS0;
  float* const WS1  = sm + SM_WS1;

  const int tid  = threadIdx.x;
  const int w    = tid >> 5;     // warp 0..15
  const int lane = tid & 31;
  const int e    = w >> 1;       // local element 0..7
  const int wh   = w & 1;        // warp-half within element
  const int g    = blockIdx.x;   // 0..127
  const int b    = g*8 + e;
  const int wr   = e * 3;        // row base in xs
  const int col  = tid & 127;
  const int rg   = tid >> 7;     // rowgroup 0..3 (setup GEMM only)
  const int c0   = wh*32 + lane; // 0..63: this thread's first GAT col
  float* const xpE = UB + e*512; // this elem's xp slot (rows r at +r*128)
  float* const gtE = UB + e*512; // this elem's gates slot

  // ---------------- setup: demo MLP + embedding -> combined ----------------
  {
    float dm[7];
    #pragma unroll
    for (int i = 0; i < 7; i++) dm[i] = demographics[b*7 + i];
    float a0 = db1[c0];
    #pragma unroll
    for (int i = 0; i < 7; i++) a0 = fmaf(dm[i], dW1[i*64 + c0], a0);
    scr[e*64 + c0] = fmaxf(a0, 0.f);
  }
  __syncthreads();
  {
    const int gi = gesture_idx[b];
    #pragma unroll
    for (int q = 0; q < 2; q++){
      int c = wh*64 + 32*q + lane;
      gtE[c] = emb_table[gi*128 + c];          // combined[0:128]
      float acc = db2[c];
      #pragma unroll 4
      for (int k = 0; k < 64; k++) acc = fmaf(scr[e*64 + k], dW2[k*128 + c], acc);
      gtE[128 + c] = acc;                      // combined[128:256]
      hs[e*128 + c] = 0.f; cs[e*128 + c] = 0.f;
    }
  }
  __syncthreads();

  // ---------------- jf = relu(combined @ jiW + jib) -> xs ----------------
  {
    float acc[6];
    #pragma unroll
    for (int i = 0; i < 6; i++) acc[i] = 0.f;
    const int ebase = rg*2;
    #pragma unroll 4
    for (int k = 0; k < 256; k++){
      float w0 = jiW[0*32768 + k*128 + col];
      float w1 = jiW[1*32768 + k*128 + col];
      float w2 = jiW[2*32768 + k*128 + col];
      #pragma unroll
      for (int ee = 0; ee < 2; ee++){
        float cv = UB[(ebase + ee)*512 + k];
        acc[ee*3+0] = fmaf(cv, w0, acc[ee*3+0]);
        acc[ee*3+1] = fmaf(cv, w1, acc[ee*3+1]);
        acc[ee*3+2] = fmaf(cv, w2, acc[ee*3+2]);
      }
    }
    __syncthreads();     // UB (combined) consumed
    #pragma unroll
    for (int ri = 0; ri < 6; ri++){
      int j = ri % 3;
      xs[(rg*6 + ri)*128 + col] = fmaxf(acc[ri] + jib[j*128 + col], 0.f);
    }
  }

  // prologue: stage GAT layer 0 into WS0
  stage8k(WS0,        gatP,        tid);
  stage8k(WS0 + 8192, gatP + 8192, tid);
  cp_commit();
  __syncthreads();

  // ---------------- time loop ----------------
  for (int t = 0; t < T_STEPS; t++){
    // ===== 3 GAT layers; layer l computes from buf (l&1 ? WS1 : WS0) =====
    #pragma unroll 1
    for (int l = 0; l < 3; l++){
      cp_wait_all();
      __syncthreads();
      // issue next phase: l<2 -> GAT layer l+1 ; l==2 -> LSTM chunk 0
      {
        float* nbuf = ((l+1)&1) ? WS1 : WS0;
        const float* src  = (l < 2) ? (gatP + (l+1)*16384)        : WihP;
        const float* src2 = (l < 2) ? (gatP + (l+1)*16384 + 8192) : WhhP;
        stage8k(nbuf,        src,  tid);
        stage8k(nbuf + 8192, src2, tid);
        cp_commit();
      }
      const float* Wl = (l&1) ? WS1 : WS0;

      // elem-local GEMM: xp[r][c0], xp[r][c0+64] for r=0..2
      {
        u64 acc[6];
        #pragma unroll
        for (int i = 0; i < 6; i++) acc[i] = 0ull;
        #pragma unroll 4
        for (int k4 = 0; k4 < 32; k4++){
          const ulonglong2 wv0 = *reinterpret_cast<const ulonglong2*>(Wl + (k4*128 + c0     )*4);
          const ulonglong2 wv1 = *reinterpret_cast<const ulonglong2*>(Wl + (k4*128 + c0 + 64)*4);
          #pragma unroll
          for (int r = 0; r < 3; r++){
            const ulonglong2 xv = *reinterpret_cast<const ulonglong2*>(&xs[(wr + r)*128 + k4*4]);
            acc[r*2+0] = ffma2(xv.x, wv0.x, acc[r*2+0]);
            acc[r*2+0] = ffma2(xv.y, wv0.y, acc[r*2+0]);
            acc[r*2+1] = ffma2(xv.x, wv1.x, acc[r*2+1]);
            acc[r*2+1] = ffma2(xv.y, wv1.y, acc[r*2+1]);
          }
        }
        #pragma unroll
        for (int r = 0; r < 3; r++){
          xpE[r*128 + c0     ] = hsum2(acc[r*2+0]);
          xpE[r*128 + c0 + 64] = hsum2(acc[r*2+1]);
        }
      }
      BAR_ELEM(e);

      // attention: 2 heads per warp
      {
        const float* as = gat_asrc + l*128;
        const float* ad = gat_adst + l*128;
        #pragma unroll
        for (int hh = 0; hh < 2; hh++){
          int h = 2*wh + hh;
          int c = h*32 + lane;
          float x0v = xpE[0*128+c], x1v = xpE[1*128+c], x2v = xpE[2*128+c];
          float av = as[c], dv = ad[c];
          u64 S01 = warpsum2(pack2(x0v*av, x1v*av));
          u64 SD2 = warpsum2(pack2(x2v*av, x2v*dv));
          float d1 = warpsum(x1v*dv);
          float s0 = lo2(S01), s1 = hi2(S01), s2 = lo2(SD2), d2 = hi2(SD2);
          float e10 = d1+s0; e10 = e10 > 0.f ? e10 : 0.2f*e10;
          float e11 = d1+s1; e11 = e11 > 0.f ? e11 : 0.2f*e11;
          float e21 = d2+s1; e21 = e21 > 0.f ? e21 : 0.2f*e21;
          float e22 = d2+s2; e22 = e22 > 0.f ? e22 : 0.2f*e22;
          float m1 = fmaxf(e10, e11);
          float p10 = __expf(e10-m1), p11 = __expf(e11-m1);
          float i1 = rcpa(p10+p11);
          float m2 = fmaxf(e21, e22);
          float p21 = __expf(e21-m2), p22 = __expf(e22-m2);
          float i2 = rcpa(p21+p22);
          xpE[1*128+c] = (p10*x0v + p11*x1v)*i1;
          xpE[2*128+c] = (p21*x1v + p22*x2v)*i2;
        }
      }
      BAR_ELEM(e);

      // bias + single-pass layernorm + relu + residual; wh0 -> rows 0,2 ; wh1 -> row 1
      {
        #pragma unroll
        for (int jj = 0; jj < 2; jj++){
          if (wh == 1 && jj == 1) break;
          int j = (wh == 0) ? (jj == 0 ? 0 : 2) : 1;
          float v[4];
          float s = 0.f, ss = 0.f;
          #pragma unroll
          for (int q = 0; q < 4; q++){
            int c = lane + 32*q;
            v[q] = xpE[j*128 + c] + gat_b[l*128 + c];
            s += v[q];
            ss = fmaf(v[q], v[q], ss);
          }
          u64 red = warpsum2(pack2(s, ss));
          float mu  = lo2(red) * (1.f/128.f);
          float var = fmaf(-mu, mu, hi2(red) * (1.f/128.f));
          float inv = rsqrtf(var + 1e-5f);
          #pragma unroll
          for (int q = 0; q < 4; q++){
            int c = lane + 32*q;
            float y = (v[q]-mu)*inv*ln_g[l*128 + c] + ln_b[l*128 + c];
            xs[(wr+j)*128 + c] = fmaxf(y, 0.f) + xs[(wr+j)*128 + c];
          }
        }
      }
      BAR_ELEM(e);
    }

    // ===== LSTM gates GEMM, K-chunked (8 chunks of 4 k4), staged weights =====
    // chunk j computes from buf: j even -> WS1, j odd -> WS0
    {
      const int ct = tid & 255;
      const int c  = ct;
      const int c2 = ct + 256;
      const int eb = (tid >> 8) * 4;           // elem base 0 or 4
      const float bs1 = bsumP[c], bs2 = bsumP[c2];
      u64 accA[4], accB[4];
      #pragma unroll
      for (int ee = 0; ee < 4; ee++){ accA[ee] = pack2(bs1, 0.f); accB[ee] = pack2(bs2, 0.f); }

      #pragma unroll 1
      for (int j = 0; j < 8; j++){
        cp_wait_all();
        __syncthreads();
        // issue next: chunks 1..7, then heads
        {
          float* nbuf = (j&1) ? WS1 : WS0;     // next compute buf
          if (j < 7){
            stage8k(nbuf,        WihP + (j+1)*8192, tid);
            stage8k(nbuf + 8192, WhhP + (j+1)*8192, tid);
          } else {
            stage8k(nbuf,        headP,        tid);
            stage8k(nbuf + 8192, headP + 8192, tid);
          }
          cp_commit();
        }
        const float* Wb = (j&1) ? WS0 : WS1;
        const int kb = j*4;

        #pragma unroll
        for (int k4l = 0; k4l < 4; k4l++){
          const ulonglong2 wiA = *reinterpret_cast<const ulonglong2*>(Wb + (k4l*512 + c )*4);
          const ulonglong2 wiB = *reinterpret_cast<const ulonglong2*>(Wb + (k4l*512 + c2)*4);
          const ulonglong2 whA = *reinterpret_cast<const ulonglong2*>(Wb + 8192 + (k4l*512 + c )*4);
          const ulonglong2 whB = *reinterpret_cast<const ulonglong2*>(Wb + 8192 + (k4l*512 + c2)*4);
          const int k4 = kb + k4l;
          #pragma unroll
          for (int ee = 0; ee < 4; ee++){
            const ulonglong2 xv = *reinterpret_cast<const ulonglong2*>(&xs[((eb+ee)*3+2)*128 + k4*4]);
            const ulonglong2 hv = *reinterpret_cast<const ulonglong2*>(&hs[(eb+ee)*128 + k4*4]);
            u64 a = accA[ee], bb = accB[ee];
            a  = ffma2(xv.x, wiA.x, a );  a  = ffma2(xv.y, wiA.y, a );
            a  = ffma2(hv.x, whA.x, a );  a  = ffma2(hv.y, whA.y, a );
            bb = ffma2(xv.x, wiB.x, bb);  bb = ffma2(xv.y, wiB.y, bb);
            bb = ffma2(hv.x, whB.x, bb);  bb = ffma2(hv.y, whB.y, bb);
            accA[ee] = a; accB[ee] = bb;
          }
        }
      }
      #pragma unroll
      for (int ee = 0; ee < 4; ee++){
        UB[(eb+ee)*512 + c]  = hsum2(accA[ee]);
        UB[(eb+ee)*512 + c2] = hsum2(accB[ee]);
      }
    }

    // ===== heads phase: wait heads weights (WS1), issue next step's GAT0 (WS0) =====
    cp_wait_all();
    __syncthreads();                            // gates visible; WS1 holds head weights
    if (t < T_STEPS - 1){
      stage8k(WS0,        gatP,        tid);    // next step GAT layer 0
      stage8k(WS0 + 8192, gatP + 8192, tid);
      cp_commit();
    }
    const float* Hb = WS1;

    // ===== LSTM pointwise (elem warps; bias folded in) =====
    {
      #pragma unroll
      for (int qq = 0; qq < 2; qq++){
        int cx = lane + 32*(2*wh + qq);
        float gi = gtE[cx];
        float gf = gtE[128 + cx];
        float gg = gtE[256 + cx];
        float go = gtE[384 + cx];
        float cn = sig_(gf)*cs[e*128 + cx] + sig_(gi)*tanh_(gg);
        float hn = sig_(go)*tanh_(cn);
        cs[e*128 + cx] = cn; hs[e*128 + cx] = hn;
      }
    }

    // ===== noise (elem-local): x += 0.05 * normal * (t/64); skip t=0 and t=63 =====
    if (t >= 1 && t < T_STEPS - 1){
      const float scale = 0.05f * (float)t * (1.0f/64.0f);
      uint32_t kt0, kt1;
      threefry(0u, 42u, 0u, (uint32_t)t, kt0, kt1);
      #pragma unroll 1
      for (int ii = wh*32 + lane; ii < 384; ii += 64){
        uint32_t m = (uint32_t)(b*384 + ii);
        uint32_t o0, o1;
        threefry(kt0, kt1, 0u, m, o0, o1);
        xs[(wr + (ii >> 7))*128 + (ii & 127)] += scale * bits_to_normal(o0 ^ o1);
      }
    }
    BAR_ELEM(e);   // hs + noised xs complete within element

    // ===== output heads (weights from staged Hb): wh0 = phys, wh1 = act =====
    float t2 = 0.f;
    if (wh == 0){
      u64 pa = 0ull, pb = 0ull;
      #pragma unroll 4
      for (int k4 = 0; k4 < 32; k4++){
        const ulonglong2 wA = *reinterpret_cast<const ulonglong2*>(Hb + (k4*64 + lane   )*4);
        const ulonglong2 wB = *reinterpret_cast<const ulonglong2*>(Hb + (k4*64 + lane+32)*4);
        const ulonglong2 hv = *reinterpret_cast<const ulonglong2*>(&hs[e*128 + k4*4]);
        pa = ffma2(hv.x, wA.x, pa); pa = ffma2(hv.y, wA.y, pa);
        pb = ffma2(hv.x, wB.x, pb); pb = ffma2(hv.y, wB.y, pb);
      }
      float p_a = fmaxf(hsum2(pa) + pb1[lane],    0.f);
      float p_b = fmaxf(hsum2(pb) + pb1[lane+32], 0.f);
      u64 P01 = warpsum2(pack2(p_a*pW2[lane*3+0] + p_b*pW2[(lane+32)*3+0],
                               p_a*pW2[lane*3+1] + p_b*pW2[(lane+32)*3+1]));
      float ph2 = warpsum(p_a*pW2[lane*3+2] + p_b*pW2[(lane+32)*3+2]);
      if (lane == 0){
        phB[e*4+0] = lo2(P01) + pb2[0];
        phB[e*4+1] = hi2(P01) + pb2[1];
        phB[e*4+2] = ph2      + pb2[2];
      }
    } else {
      u64 aa = 0ull, ab = 0ull;
      #pragma unroll 4
      for (int k4 = 0; k4 < 32; k4++){
        const ulonglong2 wA = *reinterpret_cast<const ulonglong2*>(Hb + 8192 + (k4*64 + lane   )*4);
        const ulonglong2 wB = *reinterpret_cast<const ulonglong2*>(Hb + 8192 + (k4*64 + lane+32)*4);
        const ulonglong2 hv = *reinterpret_cast<const ulonglong2*>(&hs[e*128 + k4*4]);
        aa = ffma2(hv.x, wA.x, aa); aa = ffma2(hv.y, wA.y, aa);
        ab = ffma2(hv.x, wB.x, ab); ab = ffma2(hv.y, wB.y, ab);
      }
      scr[e*64 + lane]    = fmaxf(hsum2(aa) + ab1[lane],    0.f);
      scr[e*64 + lane+32] = fmaxf(hsum2(ab) + ab1[lane+32], 0.f);
      __syncwarp();
      u64 t2a = 0ull;
      #pragma unroll
      for (int k4 = 0; k4 < 16; k4++){
        const ulonglong2 wv = *reinterpret_cast<const ulonglong2*>(aW2P + (k4*32 + lane)*4);
        const ulonglong2 sv = *reinterpret_cast<const ulonglong2*>(&scr[e*64 + k4*4]);
        t2a = ffma2(sv.x, wv.x, t2a); t2a = ffma2(sv.y, wv.y, t2a);
      }
      t2 = fmaxf(hsum2(t2a) + ab2[lane], 0.f);
    }
    BAR_ELEM(e);

    if (wh == 1){
      u64 A01 = warpsum2(pack2(t2*aW3[lane*3+0], t2*aW3[lane*3+1]));
      float a2 = warpsum(t2*aW3[lane*3+2]);
      if (lane < 3){
        float v = (lane == 0) ? (lo2(A01) + ab3[0] + 0.1f*phB[e*4+0])
                : (lane == 1) ? (hi2(A01) + ab3[1] + 0.1f*phB[e*4+1])
                              : (a2       + ab3[2] + 0.1f*phB[e*4+2]);
        out[(b*T_STEPS + t)*3 + lane] = v;
      }
    }
    BAR_ELEM(e);
  }
}

extern "C" void kernel_launch(void* const* d_in, const int* in_sizes, int n_in,
                              void* d_out, int out_size)
{
  const int off = (n_in >= 30) ? 1 : 0;
  const int*   gesture_idx  = (const int*)  d_in[0];
  const float* demographics = (const float*)d_in[1];
  const float* emb_table = (const float*)d_in[2 + off];
  const float* dW1  = (const float*)d_in[3 + off];
  const float* db1  = (const float*)d_in[4 + off];
  const float* dW2  = (const float*)d_in[5 + off];
  const float* db2  = (const float*)d_in[6 + off];
  const float* jiW  = (const float*)d_in[7 + off];
  const float* jib  = (const float*)d_in[8 + off];
  const float* gatW = (const float*)d_in[9 + off];
  const float* gat_asrc = (const float*)d_in[10 + off];
  const float* gat_adst = (const float*)d_in[11 + off];
  const float* gat_b    = (const float*)d_in[12 + off];
  const float* ln_g = (const float*)d_in[13 + off];
  const float* ln_b = (const float*)d_in[14 + off];
  const float* W_ih = (const float*)d_in[15 + off];
  const float* W_hh = (const float*)d_in[16 + off];
  const float* b_ih = (const float*)d_in[17 + off];
  const float* b_hh = (const float*)d_in[18 + off];
  const float* pW1  = (const float*)d_in[19 + off];
  const float* pb1  = (const float*)d_in[20 + off];
  const float* pW2  = (const float*)d_in[21 + off];
  const float* pb2  = (const float*)d_in[22 + off];
  const float* aW1  = (const float*)d_in[23 + off];
  const float* ab1  = (const float*)d_in[24 + off];
  const float* aW2  = (const float*)d_in[25 + off];
  const float* ab2  = (const float*)d_in[26 + off];
  const float* aW3  = (const float*)d_in[27 + off];
  const float* ab3  = (const float*)d_in[28 + off];

  const int smem_bytes = SM_TOTAL_FLOATS * 4;   // 170112
  cudaFuncSetAttribute(vkc_kernel, cudaFuncAttributeMaxDynamicSharedMemorySize, smem_bytes);

  repack_kernel<<<128, 256>>>(gatW, W_ih, W_hh, pW1, aW1, aW2, b_ih, b_hh);
  vkc_kernel<<<128, 512, smem_bytes>>>(gesture_idx, demographics, emb_table,
                           dW1, db1, dW2, db2, jiW, jib,
                           gat_asrc, gat_adst, gat_b, ln_g, ln_b,
                           pb1, pW2, pb2,
                           ab1, ab2,
                           aW3, ab3,
                           (float*)d_out);
}

// round 13
// speedup vs baseline: 1.2729x; 1.0073x over previous
#include <cuda_runtime.h>
#include <cstdint>

#define T_STEPS 64
typedef unsigned long long u64;

// ---------------- packed f32x2 helpers ----------------
__device__ __forceinline__ u64 ffma2(u64 a, u64 b, u64 c){
  u64 d; asm("fma.rn.f32x2 %0, %1, %2, %3;" : "=l"(d) : "l"(a), "l"(b), "l"(c)); return d;
}
__device__ __forceinline__ u64 addf2(u64 a, u64 b){
  u64 d; asm("add.rn.f32x2 %0, %1, %2;" : "=l"(d) : "l"(a), "l"(b)); return d;
}
__device__ __forceinline__ u64 pack2(float lo, float hi){
  u64 d; asm("mov.b64 %0, {%1, %2};" : "=l"(d) : "f"(lo), "f"(hi)); return d;
}
__device__ __forceinline__ float lo2(u64 a){ return __uint_as_float((unsigned)a); }
__device__ __forceinline__ float hi2(u64 a){ return __uint_as_float((unsigned)(a >> 32)); }
__device__ __forceinline__ float hsum2(u64 a){ return lo2(a) + hi2(a); }
__device__ __forceinline__ float rcpa(float x){
  float r; asm("rcp.approx.f32 %0, %1;" : "=f"(r) : "f"(x)); return r;
}

#define BAR_ELEM(e) asm volatile("bar.sync %0, 64;" :: "r"((e)+1) : "memory")

// ---------------- repacked weights (loop-invariant, built by pre-kernel) ----------------
__device__ __align__(16) float gatP[49152];   // [l][k4][c][4] : gatW[l][4k4+i][c]
__device__ __align__(16) float WihP[65536];   // [k4][c][4]
__device__ __align__(16) float WhhP[65536];
__device__ __align__(16) float pW1P[8192];
__device__ __align__(16) float aW1P[8192];
__device__ __align__(16) float aW2P[2048];
__device__ __align__(16) float bsumP[512];    // b_ih + b_hh

// precomputed noise: [t-1][m], t in 1..62, m in 0..393215  (97.5 MB scratch)
__device__ float noiseP[62 * 393216];

__global__ void repack_kernel(const float* __restrict__ gatW, const float* __restrict__ W_ih,
                              const float* __restrict__ W_hh, const float* __restrict__ pW1,
                              const float* __restrict__ aW1,  const float* __restrict__ aW2,
                              const float* __restrict__ b_ih, const float* __restrict__ b_hh){
  for (int idx = blockIdx.x*blockDim.x + threadIdx.x; idx < 199168; idx += gridDim.x*blockDim.x){
    if (idx < 49152){
      int f = idx; int i = f&3, c = (f>>2)&127, k4 = (f>>9)&31, l = f>>14;
      gatP[f] = gatW[(l*128 + k4*4 + i)*128 + c];
    } else if (idx < 114688){
      int f = idx - 49152; int i = f&3, c = (f>>2)&511, k4 = f>>11;
      WihP[f] = W_ih[(k4*4+i)*512 + c];
    } else if (idx < 180224){
      int f = idx - 114688; int i = f&3, c = (f>>2)&511, k4 = f>>11;
      WhhP[f] = W_hh[(k4*4+i)*512 + c];
    } else if (idx < 188416){
      int f = idx - 180224; int i = f&3, c = (f>>2)&63, k4 = f>>8;
      pW1P[f] = pW1[(k4*4+i)*64 + c];
    } else if (idx < 196608){
      int f = idx - 188416; int i = f&3, c = (f>>2)&63, k4 = f>>8;
      aW1P[f] = aW1[(k4*4+i)*64 + c];
    } else if (idx < 198656){
      int f = idx - 196608; int i = f&3, c = (f>>2)&31, k4 = f>>7;
      aW2P[f] = aW2[(k4*4+i)*32 + c];
    } else {
      int f = idx - 198656;
      bsumP[f] = b_ih[f] + b_hh[f];
    }
  }
}

// ---------------- threefry2x32 (exact JAX, partitionable path) ----------------
__device__ __forceinline__ uint32_t rotl32(uint32_t x, int d){ return __funnelshift_l(x, x, d); }

__device__ __forceinline__ void threefry(uint32_t k0, uint32_t k1, uint32_t x0, uint32_t x1,
                                         uint32_t& o0, uint32_t& o1){
  uint32_t k2 = k0 ^ k1 ^ 0x1BD11BDAu;
  x0 += k0; x1 += k1;
  #define TFR(a,b,c,d) \
    x0 += x1; x1 = rotl32(x1,a); x1 ^= x0; \
    x0 += x1; x1 = rotl32(x1,b); x1 ^= x0; \
    x0 += x1; x1 = rotl32(x1,c); x1 ^= x0; \
    x0 += x1; x1 = rotl32(x1,d); x1 ^= x0;
  TFR(13,15,26,6)  x0 += k1; x1 += k2 + 1u;
  TFR(17,29,16,24) x0 += k2; x1 += k0 + 2u;
  TFR(13,15,26,6)  x0 += k0; x1 += k1 + 3u;
  TFR(17,29,16,24) x0 += k1; x1 += k2 + 4u;
  TFR(13,15,26,6)  x0 += k2; x1 += k0 + 5u;
  #undef TFR
  o0 = x0; o1 = x1;
}

// XLA ErfInv f32 (Giles polynomial)
__device__ __forceinline__ float erfinv_f(float x){
  float w = -__logf(fmaf(-x, x, 1.0f));
  float p;
  if (w < 5.0f){
    w -= 2.5f;
    p = 2.81022636e-08f;
    p = fmaf(p, w, 3.43273939e-07f);
    p = fmaf(p, w, -3.5233877e-06f);
    p = fmaf(p, w, -4.39150654e-06f);
    p = fmaf(p, w, 0.00021858087f);
    p = fmaf(p, w, -0.00125372503f);
    p = fmaf(p, w, -0.00417768164f);
    p = fmaf(p, w, 0.246640727f);
    p = fmaf(p, w, 1.50140941f);
  } else {
    w = sqrtf(w) - 3.0f;
    p = -0.000200214257f;
    p = fmaf(p, w, 0.000100950558f);
    p = fmaf(p, w, 0.00134934322f);
    p = fmaf(p, w, -0.00367342844f);
    p = fmaf(p, w, 0.00573950773f);
    p = fmaf(p, w, -0.0076224613f);
    p = fmaf(p, w, 0.00943887047f);
    p = fmaf(p, w, 1.00167406f);
    p = fmaf(p, w, 2.83297682f);
  }
  return p * x;
}

__device__ __forceinline__ float bits_to_normal(uint32_t bits){
  float f = __uint_as_float((bits >> 9) | 0x3f800000u) - 1.0f;
  const float lo = -0.99999994f;
  float u = fmaf(f, 2.0f, lo);
  u = fmaxf(u, lo);
  return 1.41421356237309515f * erfinv_f(u);
}

// ---------------- noise precompute: noiseP[t-1][m] = scale(t)*normal(t,m) ----------------
__global__ void noise_kernel(){
  __shared__ uint32_t ks[2];
  const int t = blockIdx.y + 1;                 // 1..62
  if (threadIdx.x == 0){
    uint32_t kt0, kt1;
    threefry(0u, 42u, 0u, (uint32_t)t, kt0, kt1);   // fold_in(key(42), t)
    ks[0] = kt0; ks[1] = kt1;
  }
  __syncthreads();
  const uint32_t m = blockIdx.x * blockDim.x + threadIdx.x;   // 0..393215
  const float scale = 0.05f * (float)t * (1.0f/64.0f);
  uint32_t o0, o1;
  threefry(ks[0], ks[1], 0u, m, o0, o1);
  noiseP[(t-1)*393216 + m] = scale * bits_to_normal(o0 ^ o1);
}

__device__ __forceinline__ float warpsum(float v){
  #pragma unroll
  for (int o = 16; o > 0; o >>= 1) v += __shfl_xor_sync(0xffffffffu, v, o);
  return v;
}
__device__ __forceinline__ u64 warpsum2(u64 v){
  #pragma unroll
  for (int o = 16; o > 0; o >>= 1){
    uint32_t l = (uint32_t)v, h = (uint32_t)(v >> 32);
    l = __shfl_xor_sync(0xffffffffu, l, o);
    h = __shfl_xor_sync(0xffffffffu, h, o);
    v = addf2(v, ((u64)h << 32) | l);
  }
  return v;
}
__device__ __forceinline__ float sig_(float x){ return rcpa(1.0f + __expf(-x)); }
__device__ __forceinline__ float tanh_(float x){ return fmaf(2.0f, rcpa(1.0f + __expf(-2.0f*x)), -1.0f); }

// ---------------- mega kernel: 1 block = 8 batch elems, 2 warps/elem, 1 CTA/SM ----------------
__global__ __launch_bounds__(512, 1)
void vkc_kernel(
  const int*   __restrict__ gesture_idx,
  const float* __restrict__ demographics,
  const float* __restrict__ emb_table,
  const float* __restrict__ dW1, const float* __restrict__ db1,
  const float* __restrict__ dW2, const float* __restrict__ db2,
  const float* __restrict__ jiW, const float* __restrict__ jib,
  const float* __restrict__ gat_asrc,
  const float* __restrict__ gat_adst, const float* __restrict__ gat_b,
  const float* __restrict__ ln_g, const float* __restrict__ ln_b,
  const float* __restrict__ pb1,
  const float* __restrict__ pW2, const float* __restrict__ pb2,
  const float* __restrict__ ab1,
  const float* __restrict__ ab2,
  const float* __restrict__ aW3, const float* __restrict__ ab3,
  float* __restrict__ out)
{
  __shared__ __align__(16) float xs[24][128];   // x state: 8 elems x 3 joints
  __shared__ __align__(16) float UB[4096];      // union: xp rows / gates / combined
  __shared__ __align__(16) float hs[8][128];
  __shared__ __align__(16) float cs[8][128];
  __shared__ __align__(16) float scr[8][64];
  __shared__ __align__(16) float physs[8][4];

  const int tid  = threadIdx.x;
  const int w    = tid >> 5;     // warp 0..15
  const int lane = tid & 31;
  const int e    = w >> 1;       // local element 0..7
  const int wh   = w & 1;        // warp-half within element
  const int g    = blockIdx.x;   // 0..127
  const int b    = g*8 + e;
  const int wr   = e * 3;        // row base in xs
  const int col  = tid & 127;
  const int rg   = tid >> 7;     // rowgroup 0..3 (setup GEMM only)
  const int c0   = wh*32 + lane; // 0..63: this thread's first GAT col
  float* const xpE = UB + e*512; // this elem's xp slot (rows r at +r*128)
  float* const gtE = UB + e*512; // this elem's gates slot

  // ---------------- setup: demo MLP + embedding -> combined ----------------
  {
    float dm[7];
    #pragma unroll
    for (int i = 0; i < 7; i++) dm[i] = demographics[b*7 + i];
    float a0 = db1[c0];
    #pragma unroll
    for (int i = 0; i < 7; i++) a0 = fmaf(dm[i], dW1[i*64 + c0], a0);
    scr[e][c0] = fmaxf(a0, 0.f);
  }
  __syncthreads();
  {
    const int gi = gesture_idx[b];
    #pragma unroll
    for (int q = 0; q < 2; q++){
      int c = wh*64 + 32*q + lane;
      gtE[c] = emb_table[gi*128 + c];
      float acc = db2[c];
      #pragma unroll 4
      for (int k = 0; k < 64; k++) acc = fmaf(scr[e][k], dW2[k*128 + c], acc);
      gtE[128 + c] = acc;
      hs[e][c] = 0.f; cs[e][c] = 0.f;
    }
  }
  __syncthreads();

  // ---------------- jf = relu(combined @ jiW + jib) -> xs ----------------
  {
    float acc[6];
    #pragma unroll
    for (int i = 0; i < 6; i++) acc[i] = 0.f;
    const int ebase = rg*2;
    #pragma unroll 4
    for (int k = 0; k < 256; k++){
      float w0 = jiW[0*32768 + k*128 + col];
      float w1 = jiW[1*32768 + k*128 + col];
      float w2 = jiW[2*32768 + k*128 + col];
      #pragma unroll
      for (int ee = 0; ee < 2; ee++){
        float cv = UB[(ebase + ee)*512 + k];
        acc[ee*3+0] = fmaf(cv, w0, acc[ee*3+0]);
        acc[ee*3+1] = fmaf(cv, w1, acc[ee*3+1]);
        acc[ee*3+2] = fmaf(cv, w2, acc[ee*3+2]);
      }
    }
    __syncthreads();     // UB (combined) consumed; reused as xp below
    #pragma unroll
    for (int ri = 0; ri < 6; ri++){
      int j = ri % 3;
      xs[rg*6 + ri][col] = fmaxf(acc[ri] + jib[j*128 + col], 0.f);
    }
  }
  __syncthreads();

  // ---------------- time loop ----------------
  for (int t = 0; t < T_STEPS; t++){
    // ===== 3 GAT layers (fully elem-local) =====
    #pragma unroll 1
    for (int l = 0; l < 3; l++){
      // elem-local GEMM: xp[r][c0], xp[r][c0+64] for r=0..2
      {
        const float* Wl = gatP + l*16384;
        u64 acc[6];
        #pragma unroll
        for (int i = 0; i < 6; i++) acc[i] = 0ull;
        #pragma unroll 4
        for (int k4 = 0; k4 < 32; k4++){
          const ulonglong2 wv0 = *reinterpret_cast<const ulonglong2*>(Wl + (k4*128 + c0     )*4);
          const ulonglong2 wv1 = *reinterpret_cast<const ulonglong2*>(Wl + (k4*128 + c0 + 64)*4);
          #pragma unroll
          for (int r = 0; r < 3; r++){
            const ulonglong2 xv = *reinterpret_cast<const ulonglong2*>(&xs[wr + r][k4*4]);
            acc[r*2+0] = ffma2(xv.x, wv0.x, acc[r*2+0]);
            acc[r*2+0] = ffma2(xv.y, wv0.y, acc[r*2+0]);
            acc[r*2+1] = ffma2(xv.x, wv1.x, acc[r*2+1]);
            acc[r*2+1] = ffma2(xv.y, wv1.y, acc[r*2+1]);
          }
        }
        #pragma unroll
        for (int r = 0; r < 3; r++){
          xpE[r*128 + c0     ] = hsum2(acc[r*2+0]);
          xpE[r*128 + c0 + 64] = hsum2(acc[r*2+1]);
        }
      }
      BAR_ELEM(e);

      // attention: 2 heads per warp
      {
        const float* as = gat_asrc + l*128;
        const float* ad = gat_adst + l*128;
        #pragma unroll
        for (int hh = 0; hh < 2; hh++){
          int h = 2*wh + hh;
          int c = h*32 + lane;
          float x0v = xpE[0*128+c], x1v = xpE[1*128+c], x2v = xpE[2*128+c];
          float av = as[c], dv = ad[c];
          u64 S01 = warpsum2(pack2(x0v*av, x1v*av));
          u64 SD2 = warpsum2(pack2(x2v*av, x2v*dv));
          float d1 = warpsum(x1v*dv);
          float s0 = lo2(S01), s1 = hi2(S01), s2 = lo2(SD2), d2 = hi2(SD2);
          float e10 = d1+s0; e10 = e10 > 0.f ? e10 : 0.2f*e10;
          float e11 = d1+s1; e11 = e11 > 0.f ? e11 : 0.2f*e11;
          float e21 = d2+s1; e21 = e21 > 0.f ? e21 : 0.2f*e21;
          float e22 = d2+s2; e22 = e22 > 0.f ? e22 : 0.2f*e22;
          float m1 = fmaxf(e10, e11);
          float p10 = __expf(e10-m1), p11 = __expf(e11-m1);
          float i1 = rcpa(p10+p11);
          float m2 = fmaxf(e21, e22);
          float p21 = __expf(e21-m2), p22 = __expf(e22-m2);
          float i2 = rcpa(p21+p22);
          xpE[1*128+c] = (p10*x0v + p11*x1v)*i1;
          xpE[2*128+c] = (p21*x1v + p22*x2v)*i2;
        }
      }
      BAR_ELEM(e);

      // bias + single-pass layernorm + relu + residual; wh0 -> rows 0,2 ; wh1 -> row 1
      {
        #pragma unroll
        for (int jj = 0; jj < 2; jj++){
          if (wh == 1 && jj == 1) break;
          int j = (wh == 0) ? (jj == 0 ? 0 : 2) : 1;
          float v[4];
          float s = 0.f, ss = 0.f;
          #pragma unroll
          for (int q = 0; q < 4; q++){
            int c = lane + 32*q;
            v[q] = xpE[j*128 + c] + gat_b[l*128 + c];
            s += v[q];
            ss = fmaf(v[q], v[q], ss);
          }
          u64 red = warpsum2(pack2(s, ss));
          float mu  = lo2(red) * (1.f/128.f);
          float var = fmaf(-mu, mu, hi2(red) * (1.f/128.f));
          float inv = rsqrtf(var + 1e-5f);
          #pragma unroll
          for (int q = 0; q < 4; q++){
            int c = lane + 32*q;
            float y = (v[q]-mu)*inv*ln_g[l*128 + c] + ln_b[l*128 + c];
            xs[wr+j][c] = fmaxf(y, 0.f) + xs[wr+j][c];
          }
        }
      }
      __syncthreads();
    }

    // ===== LSTM gates GEMM: half 0 (tid<256) -> elems 0-3, half 1 -> elems 4-7 =====
    {
      const int ct = tid & 255;
      const int c  = ct;
      const int c2 = ct + 256;
      const int eb = (tid >> 8) * 4;
      const float bs1 = bsumP[c], bs2 = bsumP[c2];
      u64 accA[4], accB[4];
      #pragma unroll
      for (int ee = 0; ee < 4; ee++){ accA[ee] = pack2(bs1, 0.f); accB[ee] = pack2(bs2, 0.f); }
      #pragma unroll 2
      for (int k4 = 0; k4 < 32; k4++){
        const ulonglong2 wiA = *reinterpret_cast<const ulonglong2*>(WihP + (k4*512 + c )*4);
        const ulonglong2 wiB = *reinterpret_cast<const ulonglong2*>(WihP + (k4*512 + c2)*4);
        const ulonglong2 whA = *reinterpret_cast<const ulonglong2*>(WhhP + (k4*512 + c )*4);
        const ulonglong2 whB = *reinterpret_cast<const ulonglong2*>(WhhP + (k4*512 + c2)*4);
        #pragma unroll
        for (int ee = 0; ee < 4; ee++){
          const ulonglong2 xv = *reinterpret_cast<const ulonglong2*>(&xs[(eb+ee)*3+2][k4*4]);
          const ulonglong2 hv = *reinterpret_cast<const ulonglong2*>(&hs[eb+ee][k4*4]);
          u64 a = accA[ee], bb = accB[ee];
          a  = ffma2(xv.x, wiA.x, a );  a  = ffma2(xv.y, wiA.y, a );
          a  = ffma2(hv.x, whA.x, a );  a  = ffma2(hv.y, whA.y, a );
          bb = ffma2(xv.x, wiB.x, bb);  bb = ffma2(xv.y, wiB.y, bb);
          bb = ffma2(hv.x, whB.x, bb);  bb = ffma2(hv.y, whB.y, bb);
          accA[ee] = a; accB[ee] = bb;
        }
      }
      #pragma unroll
      for (int ee = 0; ee < 4; ee++){
        UB[(eb+ee)*512 + c]  = hsum2(accA[ee]);
        UB[(eb+ee)*512 + c2] = hsum2(accB[ee]);
      }
    }
    __syncthreads();

    // ===== LSTM pointwise (elem warps; bias folded in) =====
    {
      #pragma unroll
      for (int qq = 0; qq < 2; qq++){
        int cx = lane + 32*(2*wh + qq);
        float gi = gtE[cx];
        float gf = gtE[128 + cx];
        float gg = gtE[256 + cx];
        float go = gtE[384 + cx];
        float cn = sig_(gf)*cs[e][cx] + sig_(gi)*tanh_(gg);
        float hn = sig_(go)*tanh_(cn);
        cs[e][cx] = cn; hs[e][cx] = hn;
      }
    }

    // ===== noise (precomputed): x += noiseP[t-1][b*384 + ii]; skip t=0 and t=63 =====
    if (t >= 1 && t < T_STEPS - 1){
      const float* np = noiseP + (t-1)*393216 + b*384;
      #pragma unroll
      for (int r = 0; r < 3; r++){
        int ii = wh*32 + lane + r*128;
        float n0 = np[ii];
        float n1 = np[ii + 64];
        xs[wr + (ii >> 7)][ii & 127]               += n0;
        xs[wr + ((ii+64) >> 7)][(ii+64) & 127]     += n1;
      }
    }
    BAR_ELEM(e);   // hs + noised xs complete within element

    // ===== output heads: wh0 = phys path, wh1 = act path =====
    float t2 = 0.f;
    if (wh == 0){
      u64 pa = 0ull, pb = 0ull;
      #pragma unroll 4
      for (int k4 = 0; k4 < 32; k4++){
        const ulonglong2 wA = *reinterpret_cast<const ulonglong2*>(pW1P + (k4*64 + lane   )*4);
        const ulonglong2 wB = *reinterpret_cast<const ulonglong2*>(pW1P + (k4*64 + lane+32)*4);
        const ulonglong2 hv = *reinterpret_cast<const ulonglong2*>(&hs[e][k4*4]);
        pa = ffma2(hv.x, wA.x, pa); pa = ffma2(hv.y, wA.y, pa);
        pb = ffma2(hv.x, wB.x, pb); pb = ffma2(hv.y, wB.y, pb);
      }
      float p_a = fmaxf(hsum2(pa) + pb1[lane],    0.f);
      float p_b = fmaxf(hsum2(pb) + pb1[lane+32], 0.f);
      u64 P01 = warpsum2(pack2(p_a*pW2[lane*3+0] + p_b*pW2[(lane+32)*3+0],
                               p_a*pW2[lane*3+1] + p_b*pW2[(lane+32)*3+1]));
      float ph2 = warpsum(p_a*pW2[lane*3+2] + p_b*pW2[(lane+32)*3+2]);
      if (lane == 0){
        physs[e][0] = lo2(P01) + pb2[0];
        physs[e][1] = hi2(P01) + pb2[1];
        physs[e][2] = ph2      + pb2[2];
      }
    } else {
      u64 aa = 0ull, ab = 0ull;
      #pragma unroll 4
      for (int k4 = 0; k4 < 32; k4++){
        const ulonglong2 wA = *reinterpret_cast<const ulonglong2*>(aW1P + (k4*64 + lane   )*4);
        const ulonglong2 wB = *reinterpret_cast<const ulonglong2*>(aW1P + (k4*64 + lane+32)*4);
        const ulonglong2 hv = *reinterpret_cast<const ulonglong2*>(&hs[e][k4*4]);
        aa = ffma2(hv.x, wA.x, aa); aa = ffma2(hv.y, wA.y, aa);
        ab = ffma2(hv.x, wB.x, ab); ab = ffma2(hv.y, wB.y, ab);
      }
      scr[e][lane]    = fmaxf(hsum2(aa) + ab1[lane],    0.f);
      scr[e][lane+32] = fmaxf(hsum2(ab) + ab1[lane+32], 0.f);
      __syncwarp();
      u64 t2a = 0ull;
      #pragma unroll
      for (int k4 = 0; k4 < 16; k4++){
        const ulonglong2 wv = *reinterpret_cast<const ulonglong2*>(aW2P + (k4*32 + lane)*4);
        const ulonglong2 sv = *reinterpret_cast<const ulonglong2*>(&scr[e][k4*4]);
        t2a = ffma2(sv.x, wv.x, t2a); t2a = ffma2(sv.y, wv.y, t2a);
      }
      t2 = fmaxf(hsum2(t2a) + ab2[lane], 0.f);
    }
    BAR_ELEM(e);

    if (wh == 1){
      u64 A01 = warpsum2(pack2(t2*aW3[lane*3+0], t2*aW3[lane*3+1]));
      float a2 = warpsum(t2*aW3[lane*3+2]);
      if (lane < 3){
        float v = (lane == 0) ? (lo2(A01) + ab3[0] + 0.1f*physs[e][0])
                : (lane == 1) ? (hi2(A01) + ab3[1] + 0.1f*physs[e][1])
                              : (a2       + ab3[2] + 0.1f*physs[e][2]);
        out[(b*T_STEPS + t)*3 + lane] = v;
      }
    }
    BAR_ELEM(e);   // elem may drift into next step's GAT (own slots only)
  }
}

extern "C" void kernel_launch(void* const* d_in, const int* in_sizes, int n_in,
                              void* d_out, int out_size)
{
  const int off = (n_in >= 30) ? 1 : 0;
  const int*   gesture_idx  = (const int*)  d_in[0];
  const float* demographics = (const float*)d_in[1];
  const float* emb_table = (const float*)d_in[2 + off];
  const float* dW1  = (const float*)d_in[3 + off];
  const float* db1  = (const float*)d_in[4 + off];
  const float* dW2  = (const float*)d_in[5 + off];
  const float* db2  = (const float*)d_in[6 + off];
  const float* jiW  = (const float*)d_in[7 + off];
  const float* jib  = (const float*)d_in[8 + off];
  const float* gatW = (const float*)d_in[9 + off];
  const float* gat_asrc = (const float*)d_in[10 + off];
  const float* gat_adst = (const float*)d_in[11 + off];
  const float* gat_b    = (const float*)d_in[12 + off];
  const float* ln_g = (const float*)d_in[13 + off];
  const float* ln_b = (const float*)d_in[14 + off];
  const float* W_ih = (const float*)d_in[15 + off];
  const float* W_hh = (const float*)d_in[16 + off];
  const float* b_ih = (const float*)d_in[17 + off];
  const float* b_hh = (const float*)d_in[18 + off];
  const float* pW1  = (const float*)d_in[19 + off];
  const float* pb1  = (const float*)d_in[20 + off];
  const float* pW2  = (const float*)d_in[21 + off];
  const float* pb2  = (const float*)d_in[22 + off];
  const float* aW1  = (const float*)d_in[23 + off];
  const float* ab1  = (const float*)d_in[24 + off];
  const float* aW2  = (const float*)d_in[25 + off];
  const float* ab2  = (const float*)d_in[26 + off];
  const float* aW3  = (const float*)d_in[27 + off];
  const float* ab3  = (const float*)d_in[28 + off];

  repack_kernel<<<128, 256>>>(gatW, W_ih, W_hh, pW1, aW1, aW2, b_ih, b_hh);
  noise_kernel<<<dim3(1536, 62, 1), 256>>>();
  vkc_kernel<<<128, 512>>>(gesture_idx, demographics, emb_table,
                           dW1, db1, dW2, db2, jiW, jib,
                           gat_asrc, gat_adst, gat_b, ln_g, ln_b,
                           pb1, pW2, pb2,
                           ab1, ab2,
                           aW3, ab3,
                           (float*)d_out);
}

// round 15
// speedup vs baseline: 1.4010x; 1.1006x over previous
#include <cuda_runtime.h>
#include <cstdint>

#define T_STEPS 64
typedef unsigned long long u64;

// ---------------- packed f32x2 helpers ----------------
__device__ __forceinline__ u64 ffma2(u64 a, u64 b, u64 c){
  u64 d; asm("fma.rn.f32x2 %0, %1, %2, %3;" : "=l"(d) : "l"(a), "l"(b), "l"(c)); return d;
}
__device__ __forceinline__ u64 addf2(u64 a, u64 b){
  u64 d; asm("add.rn.f32x2 %0, %1, %2;" : "=l"(d) : "l"(a), "l"(b)); return d;
}
__device__ __forceinline__ u64 pack2(float lo, float hi){
  u64 d; asm("mov.b64 %0, {%1, %2};" : "=l"(d) : "f"(lo), "f"(hi)); return d;
}
__device__ __forceinline__ float lo2(u64 a){ return __uint_as_float((unsigned)a); }
__device__ __forceinline__ float hi2(u64 a){ return __uint_as_float((unsigned)(a >> 32)); }
__device__ __forceinline__ float hsum2(u64 a){ return lo2(a) + hi2(a); }
__device__ __forceinline__ float rcpa(float x){
  float r; asm("rcp.approx.f32 %0, %1;" : "=f"(r) : "f"(x)); return r;
}

#define BAR_ELEM(e) asm volatile("bar.sync %0, 64;" :: "r"((e)+1) : "memory")

// ---------------- repacked weights (loop-invariant, built by pre-kernel) ----------------
__device__ __align__(16) float gatP[49152];   // [l][k4][c][4] : gatW[l][4k4+i][c]
__device__ __align__(16) float WihP[65536];   // [k4][c][4]
__device__ __align__(16) float WhhP[65536];
__device__ __align__(16) float pW1P[8192];
__device__ __align__(16) float aW1P[8192];
__device__ __align__(16) float aW2P[2048];
__device__ __align__(16) float bsumP[512];    // b_ih + b_hh

__global__ void repack_kernel(const float* __restrict__ gatW, const float* __restrict__ W_ih,
                              const float* __restrict__ W_hh, const float* __restrict__ pW1,
                              const float* __restrict__ aW1,  const float* __restrict__ aW2,
                              const float* __restrict__ b_ih, const float* __restrict__ b_hh){
  for (int idx = blockIdx.x*blockDim.x + threadIdx.x; idx < 199168; idx += gridDim.x*blockDim.x){
    if (idx < 49152){
      int f = idx; int i = f&3, c = (f>>2)&127, k4 = (f>>9)&31, l = f>>14;
      gatP[f] = gatW[(l*128 + k4*4 + i)*128 + c];
    } else if (idx < 114688){
      int f = idx - 49152; int i = f&3, c = (f>>2)&511, k4 = f>>11;
      WihP[f] = W_ih[(k4*4+i)*512 + c];
    } else if (idx < 180224){
      int f = idx - 114688; int i = f&3, c = (f>>2)&511, k4 = f>>11;
      WhhP[f] = W_hh[(k4*4+i)*512 + c];
    } else if (idx < 188416){
      int f = idx - 180224; int i = f&3, c = (f>>2)&63, k4 = f>>8;
      pW1P[f] = pW1[(k4*4+i)*64 + c];
    } else if (idx < 196608){
      int f = idx - 188416; int i = f&3, c = (f>>2)&63, k4 = f>>8;
      aW1P[f] = aW1[(k4*4+i)*64 + c];
    } else if (idx < 198656){
      int f = idx - 196608; int i = f&3, c = (f>>2)&31, k4 = f>>7;
      aW2P[f] = aW2[(k4*4+i)*32 + c];
    } else {
      int f = idx - 198656;
      bsumP[f] = b_ih[f] + b_hh[f];
    }
  }
}

// ---------------- threefry2x32 (exact JAX, partitionable path) ----------------
__device__ __forceinline__ uint32_t rotl32(uint32_t x, int d){ return __funnelshift_l(x, x, d); }

__device__ __forceinline__ void threefry(uint32_t k0, uint32_t k1, uint32_t x0, uint32_t x1,
                                         uint32_t& o0, uint32_t& o1){
  uint32_t k2 = k0 ^ k1 ^ 0x1BD11BDAu;
  x0 += k0; x1 += k1;
  #define TFR(a,b,c,d) \
    x0 += x1; x1 = rotl32(x1,a); x1 ^= x0; \
    x0 += x1; x1 = rotl32(x1,b); x1 ^= x0; \
    x0 += x1; x1 = rotl32(x1,c); x1 ^= x0; \
    x0 += x1; x1 = rotl32(x1,d); x1 ^= x0;
  TFR(13,15,26,6)  x0 += k1; x1 += k2 + 1u;
  TFR(17,29,16,24) x0 += k2; x1 += k0 + 2u;
  TFR(13,15,26,6)  x0 += k0; x1 += k1 + 3u;
  TFR(17,29,16,24) x0 += k1; x1 += k2 + 4u;
  TFR(13,15,26,6)  x0 += k2; x1 += k0 + 5u;
  #undef TFR
  o0 = x0; o1 = x1;
}

// XLA ErfInv f32 (Giles polynomial)
__device__ __forceinline__ float erfinv_f(float x){
  float w = -__logf(fmaf(-x, x, 1.0f));
  float p;
  if (w < 5.0f){
    w -= 2.5f;
    p = 2.81022636e-08f;
    p = fmaf(p, w, 3.43273939e-07f);
    p = fmaf(p, w, -3.5233877e-06f);
    p = fmaf(p, w, -4.39150654e-06f);
    p = fmaf(p, w, 0.00021858087f);
    p = fmaf(p, w, -0.00125372503f);
    p = fmaf(p, w, -0.00417768164f);
    p = fmaf(p, w, 0.246640727f);
    p = fmaf(p, w, 1.50140941f);
  } else {
    w = sqrtf(w) - 3.0f;
    p = -0.000200214257f;
    p = fmaf(p, w, 0.000100950558f);
    p = fmaf(p, w, 0.00134934322f);
    p = fmaf(p, w, -0.00367342844f);
    p = fmaf(p, w, 0.00573950773f);
    p = fmaf(p, w, -0.0076224613f);
    p = fmaf(p, w, 0.00943887047f);
    p = fmaf(p, w, 1.00167406f);
    p = fmaf(p, w, 2.83297682f);
  }
  return p * x;
}

__device__ __forceinline__ float bits_to_normal(uint32_t bits){
  float f = __uint_as_float((bits >> 9) | 0x3f800000u) - 1.0f;
  const float lo = -0.99999994f;
  float u = fmaf(f, 2.0f, lo);
  u = fmaxf(u, lo);
  return 1.41421356237309515f * erfinv_f(u);
}

__device__ __forceinline__ float warpsum(float v){
  #pragma unroll
  for (int o = 16; o > 0; o >>= 1) v += __shfl_xor_sync(0xffffffffu, v, o);
  return v;
}
__device__ __forceinline__ u64 warpsum2(u64 v){
  #pragma unroll
  for (int o = 16; o > 0; o >>= 1){
    uint32_t l = (uint32_t)v, h = (uint32_t)(v >> 32);
    l = __shfl_xor_sync(0xffffffffu, l, o);
    h = __shfl_xor_sync(0xffffffffu, h, o);
    v = addf2(v, ((u64)h << 32) | l);
  }
  return v;
}
__device__ __forceinline__ float sig_(float x){ return rcpa(1.0f + __expf(-x)); }
__device__ __forceinline__ float tanh_(float x){ return fmaf(2.0f, rcpa(1.0f + __expf(-2.0f*x)), -1.0f); }
__device__ __forceinline__ float leaky_(float x){ return x > 0.f ? x : 0.2f*x; }

// ---------------- mega kernel: 1 block = 4 batch elems, 2 warps/elem, 2 CTA/SM ----------------
__global__ __launch_bounds__(256, 2)
void vkc_kernel(
  const int*   __restrict__ gesture_idx,
  const float* __restrict__ demographics,
  const float* __restrict__ emb_table,
  const float* __restrict__ dW1, const float* __restrict__ db1,
  const float* __restrict__ dW2, const float* __restrict__ db2,
  const float* __restrict__ jiW, const float* __restrict__ jib,
  const float* __restrict__ gat_asrc,
  const float* __restrict__ gat_adst, const float* __restrict__ gat_b,
  const float* __restrict__ ln_g, const float* __restrict__ ln_b,
  const float* __restrict__ pb1,
  const float* __restrict__ pW2, const float* __restrict__ pb2,
  const float* __restrict__ ab1,
  const float* __restrict__ ab2,
  const float* __restrict__ aW3, const float* __restrict__ ab3,
  float* __restrict__ out)
{
  __shared__ __align__(16) float xs[12][128];     // x state: 4 elems x 3 joints
  __shared__ __align__(16) float gates[4][512];   // also comb[4][256] in setup
  __shared__ __align__(16) float hs[4][128];
  __shared__ __align__(16) float cs[4][128];
  __shared__ __align__(16) float scr[4][64];
  __shared__ __align__(16) u64   statU[4][6];     // LN partials: [e][wh*3 + row]
  __shared__              float physs[4][3];

  const int tid  = threadIdx.x;
  const int w    = tid >> 5;     // warp 0..7
  const int lane = tid & 31;
  const int e    = w >> 1;       // local element 0..3
  const int wh   = w & 1;        // warp-half within element
  const int g    = blockIdx.x;   // 0..255
  const int b    = g*4 + e;
  const int wr   = e * 3;        // row base in xs
  const int col  = tid & 127;
  const int rg   = tid >> 7;     // rowgroup 0/1 (setup GEMM only)
  const int c0   = wh*32 + lane; // first col (head wh)
  const int c1   = c0 + 64;      // second col (head wh+2)
  float* const gtE = gates[e];

  // ---------------- setup: demo MLP + embedding -> combined ----------------
  {
    float dm[7];
    #pragma unroll
    for (int i = 0; i < 7; i++) dm[i] = demographics[b*7 + i];
    float a0 = db1[c0];
    #pragma unroll
    for (int i = 0; i < 7; i++) a0 = fmaf(dm[i], dW1[i*64 + c0], a0);
    scr[e][c0] = fmaxf(a0, 0.f);
  }
  __syncthreads();
  {
    const int gi = gesture_idx[b];
    #pragma unroll
    for (int q = 0; q < 2; q++){
      int c = wh*64 + 32*q + lane;
      gtE[c] = emb_table[gi*128 + c];
      float acc = db2[c];
      #pragma unroll 4
      for (int k = 0; k < 64; k++) acc = fmaf(scr[e][k], dW2[k*128 + c], acc);
      gtE[128 + c] = acc;
      hs[e][c] = 0.f; cs[e][c] = 0.f;
    }
  }
  __syncthreads();

  // ---------------- jf = relu(combined @ jiW + jib) -> xs ----------------
  {
    float acc[6];
    #pragma unroll
    for (int i = 0; i < 6; i++) acc[i] = 0.f;
    const int ebase = rg*2;
    #pragma unroll 4
    for (int k = 0; k < 256; k++){
      float w0 = jiW[0*32768 + k*128 + col];
      float w1 = jiW[1*32768 + k*128 + col];
      float w2 = jiW[2*32768 + k*128 + col];
      #pragma unroll
      for (int ee = 0; ee < 2; ee++){
        float cv = gates[ebase + ee][k];
        acc[ee*3+0] = fmaf(cv, w0, acc[ee*3+0]);
        acc[ee*3+1] = fmaf(cv, w1, acc[ee*3+1]);
        acc[ee*3+2] = fmaf(cv, w2, acc[ee*3+2]);
      }
    }
    #pragma unroll
    for (int ri = 0; ri < 6; ri++){
      int j = ri % 3;
      xs[rg*6 + ri][col] = fmaxf(acc[ri] + jib[j*128 + col], 0.f);
    }
  }
  __syncthreads();

  // ---------------- time loop ----------------
  for (int t = 0; t < T_STEPS; t++){
    // ===== 3 GAT layers (register-resident: GEMM -> attention -> LN, no xp buffer) =====
    #pragma unroll 1
    for (int l = 0; l < 3; l++){
      // GEMM: thread -> rows 0..2, cols c0 (head wh) and c1 (head wh+2), in regs
      u64 acc[6];
      #pragma unroll
      for (int i = 0; i < 6; i++) acc[i] = 0ull;
      {
        const float* Wl = gatP + l*16384;
        #pragma unroll 4
        for (int k4 = 0; k4 < 32; k4++){
          const ulonglong2 wv0 = *reinterpret_cast<const ulonglong2*>(Wl + (k4*128 + c0)*4);
          const ulonglong2 wv1 = *reinterpret_cast<const ulonglong2*>(Wl + (k4*128 + c1)*4);
          #pragma unroll
          for (int r = 0; r < 3; r++){
            const ulonglong2 xv = *reinterpret_cast<const ulonglong2*>(&xs[wr + r][k4*4]);
            acc[r*2+0] = ffma2(xv.x, wv0.x, acc[r*2+0]);
            acc[r*2+0] = ffma2(xv.y, wv0.y, acc[r*2+0]);
            acc[r*2+1] = ffma2(xv.x, wv1.x, acc[r*2+1]);
            acc[r*2+1] = ffma2(xv.y, wv1.y, acc[r*2+1]);
          }
        }
      }
      float x0a = hsum2(acc[0]), x0b = hsum2(acc[1]);
      float x1a = hsum2(acc[2]), x1b = hsum2(acc[3]);
      float x2a = hsum2(acc[4]), x2b = hsum2(acc[5]);

      // attention dots (packed: lo=head wh side a, hi=head wh+2 side b)
      float v0a, v1a, v2a, v0b, v1b, v2b;   // post-attention values
      {
        const float asa = gat_asrc[l*128 + c0], asb = gat_asrc[l*128 + c1];
        const float ada = gat_adst[l*128 + c0], adb = gat_adst[l*128 + c1];
        u64 S0 = warpsum2(pack2(x0a*asa, x0b*asb));
        u64 S1 = warpsum2(pack2(x1a*asa, x1b*asb));
        u64 S2 = warpsum2(pack2(x2a*asa, x2b*asb));
        u64 D1 = warpsum2(pack2(x1a*ada, x1b*adb));
        u64 D2 = warpsum2(pack2(x2a*ada, x2b*adb));
        // side a
        {
          float e10 = leaky_(lo2(D1)+lo2(S0)), e11 = leaky_(lo2(D1)+lo2(S1));
          float e21 = leaky_(lo2(D2)+lo2(S1)), e22 = leaky_(lo2(D2)+lo2(S2));
          float m1 = fmaxf(e10, e11);
          float p10 = __expf(e10-m1), p11 = __expf(e11-m1);
          float i1 = rcpa(p10+p11);
          float m2 = fmaxf(e21, e22);
          float p21 = __expf(e21-m2), p22 = __expf(e22-m2);
          float i2 = rcpa(p21+p22);
          v0a = x0a;
          v1a = (p10*x0a + p11*x1a)*i1;
          v2a = (p21*x1a + p22*x2a)*i2;
        }
        // side b
        {
          float e10 = leaky_(hi2(D1)+hi2(S0)), e11 = leaky_(hi2(D1)+hi2(S1));
          float e21 = leaky_(hi2(D2)+hi2(S1)), e22 = leaky_(hi2(D2)+hi2(S2));
          float m1 = fmaxf(e10, e11);
          float p10 = __expf(e10-m1), p11 = __expf(e11-m1);
          float i1 = rcpa(p10+p11);
          float m2 = fmaxf(e21, e22);
          float p21 = __expf(e21-m2), p22 = __expf(e22-m2);
          float i2 = rcpa(p21+p22);
          v0b = x0b;
          v1b = (p10*x0b + p11*x1b)*i1;
          v2b = (p21*x1b + p22*x2b)*i2;
        }
      }

      // bias + LN stats (both warps, all 3 rows; cross-warp exchange via statU)
      {
        const float gba = gat_b[l*128 + c0], gbb = gat_b[l*128 + c1];
        v0a += gba; v0b += gbb;
        v1a += gba; v1b += gbb;
        v2a += gba; v2b += gbb;
        u64 R0 = warpsum2(pack2(v0a + v0b, fmaf(v0a, v0a, v0b*v0b)));
        u64 R1 = warpsum2(pack2(v1a + v1b, fmaf(v1a, v1a, v1b*v1b)));
        u64 R2 = warpsum2(pack2(v2a + v2b, fmaf(v2a, v2a, v2b*v2b)));
        if (lane == 0){
          statU[e][wh*3 + 0] = R0;
          statU[e][wh*3 + 1] = R1;
          statU[e][wh*3 + 2] = R2;
        }
        BAR_ELEM(e);
        const int ow = (1 - wh)*3;
        u64 T0 = addf2(R0, statU[e][ow + 0]);
        u64 T1 = addf2(R1, statU[e][ow + 1]);
        u64 T2 = addf2(R2, statU[e][ow + 2]);
        const float lga = ln_g[l*128 + c0], lgb = ln_g[l*128 + c1];
        const float lba = ln_b[l*128 + c0], lbb = ln_b[l*128 + c1];
        float mu, inv;
        #define LN_ROW(Tr, va, vb, row)                                        \
        {                                                                      \
          mu  = lo2(Tr) * (1.f/128.f);                                         \
          float var = fmaf(-mu, mu, hi2(Tr) * (1.f/128.f));                    \
          inv = rsqrtf(var + 1e-5f);                                           \
          float ya = fmaf((va - mu)*inv, lga, lba);                            \
          float yb = fmaf((vb - mu)*inv, lgb, lbb);                            \
          xs[wr + row][c0] = fmaxf(ya, 0.f) + xs[wr + row][c0];                \
          xs[wr + row][c1] = fmaxf(yb, 0.f) + xs[wr + row][c1];                \
        }
        LN_ROW(T0, v0a, v0b, 0)
        LN_ROW(T1, v1a, v1b, 1)
        LN_ROW(T2, v2a, v2b, 2)
        #undef LN_ROW
      }
      BAR_ELEM(e);   // xs ready for next layer's GEMM (elem-local)
    }

    __syncthreads();   // all elems' xs row2 + hs ready for block-wide LSTM GEMM

    // ===== LSTM gates GEMM (f32x2): gates[4][512] = w@W_ih + h@W_hh + bsum =====
    {
      const int c  = tid;
      const int c2 = tid + 256;
      u64 accA[4], accB[4];
      #pragma unroll
      for (int ee = 0; ee < 4; ee++){ accA[ee] = pack2(bsumP[c], 0.f); accB[ee] = pack2(bsumP[c2], 0.f); }
      #pragma unroll 2
      for (int k4 = 0; k4 < 32; k4++){
        const ulonglong2 wiA = *reinterpret_cast<const ulonglong2*>(WihP + (k4*512 + c )*4);
        const ulonglong2 wiB = *reinterpret_cast<const ulonglong2*>(WihP + (k4*512 + c2)*4);
        const ulonglong2 whA = *reinterpret_cast<const ulonglong2*>(WhhP + (k4*512 + c )*4);
        const ulonglong2 whB = *reinterpret_cast<const ulonglong2*>(WhhP + (k4*512 + c2)*4);
        #pragma unroll
        for (int ee = 0; ee < 4; ee++){
          const ulonglong2 xv = *reinterpret_cast<const ulonglong2*>(&xs[ee*3+2][k4*4]);
          const ulonglong2 hv = *reinterpret_cast<const ulonglong2*>(&hs[ee][k4*4]);
          u64 a = accA[ee], bb = accB[ee];
          a  = ffma2(xv.x, wiA.x, a );  a  = ffma2(xv.y, wiA.y, a );
          a  = ffma2(hv.x, whA.x, a );  a  = ffma2(hv.y, whA.y, a );
          bb = ffma2(xv.x, wiB.x, bb);  bb = ffma2(xv.y, wiB.y, bb);
          bb = ffma2(hv.x, whB.x, bb);  bb = ffma2(hv.y, whB.y, bb);
          accA[ee] = a; accB[ee] = bb;
        }
      }
      #pragma unroll
      for (int ee = 0; ee < 4; ee++){
        gates[ee][c]  = hsum2(accA[ee]);
        gates[ee][c2] = hsum2(accB[ee]);
      }
    }
    __syncthreads();

    // ===== LSTM pointwise (elem warps; bias folded in) =====
    {
      #pragma unroll
      for (int qq = 0; qq < 2; qq++){
        int cx = lane + 32*(2*wh + qq);
        float gi = gtE[cx];
        float gf = gtE[128 + cx];
        float gg = gtE[256 + cx];
        float go = gtE[384 + cx];
        float cn = sig_(gf)*cs[e][cx] + sig_(gi)*tanh_(gg);
        float hn = sig_(go)*tanh_(cn);
        cs[e][cx] = cn; hs[e][cx] = hn;
      }
    }

    // ===== noise (elem-local): x += 0.05 * normal * (t/64); skip t=0 and t=63 =====
    if (t >= 1 && t < T_STEPS - 1){
      const float scale = 0.05f * (float)t * (1.0f/64.0f);
      uint32_t kt0, kt1;
      threefry(0u, 42u, 0u, (uint32_t)t, kt0, kt1);
      #pragma unroll 1
      for (int ii = wh*32 + lane; ii < 384; ii += 64){
        uint32_t m = (uint32_t)(b*384 + ii);
        uint32_t o0, o1;
        threefry(kt0, kt1, 0u, m, o0, o1);
        xs[wr + (ii >> 7)][ii & 127] += scale * bits_to_normal(o0 ^ o1);
      }
    }
    BAR_ELEM(e);   // hs + noised xs complete within element

    // ===== output heads: wh0 = phys path, wh1 = act path =====
    float t2 = 0.f;
    if (wh == 0){
      u64 pa = 0ull, pb = 0ull;
      #pragma unroll 4
      for (int k4 = 0; k4 < 32; k4++){
        const ulonglong2 wA = *reinterpret_cast<const ulonglong2*>(pW1P + (k4*64 + lane   )*4);
        const ulonglong2 wB = *reinterpret_cast<const ulonglong2*>(pW1P + (k4*64 + lane+32)*4);
        const ulonglong2 hv = *reinterpret_cast<const ulonglong2*>(&hs[e][k4*4]);
        pa = ffma2(hv.x, wA.x, pa); pa = ffma2(hv.y, wA.y, pa);
        pb = ffma2(hv.x, wB.x, pb); pb = ffma2(hv.y, wB.y, pb);
      }
      float p_a = fmaxf(hsum2(pa) + pb1[lane],    0.f);
      float p_b = fmaxf(hsum2(pb) + pb1[lane+32], 0.f);
      u64 P01 = warpsum2(pack2(p_a*pW2[lane*3+0] + p_b*pW2[(lane+32)*3+0],
                               p_a*pW2[lane*3+1] + p_b*pW2[(lane+32)*3+1]));
      float ph2 = warpsum(p_a*pW2[lane*3+2] + p_b*pW2[(lane+32)*3+2]);
      if (lane == 0){
        physs[e][0] = lo2(P01) + pb2[0];
        physs[e][1] = hi2(P01) + pb2[1];
        physs[e][2] = ph2      + pb2[2];
      }
    } else {
      u64 aa = 0ull, ab = 0ull;
      #pragma unroll 4
      for (int k4 = 0; k4 < 32; k4++){
        const ulonglong2 wA = *reinterpret_cast<const ulonglong2*>(aW1P + (k4*64 + lane   )*4);
        const ulonglong2 wB = *reinterpret_cast<const ulonglong2*>(aW1P + (k4*64 + lane+32)*4);
        const ulonglong2 hv = *reinterpret_cast<const ulonglong2*>(&hs[e][k4*4]);
        aa = ffma2(hv.x, wA.x, aa); aa = ffma2(hv.y, wA.y, aa);
        ab = ffma2(hv.x, wB.x, ab); ab = ffma2(hv.y, wB.y, ab);
      }
      scr[e][lane]    = fmaxf(hsum2(aa) + ab1[lane],    0.f);
      scr[e][lane+32] = fmaxf(hsum2(ab) + ab1[lane+32], 0.f);
      __syncwarp();
      u64 t2a = 0ull;
      #pragma unroll
      for (int k4 = 0; k4 < 16; k4++){
        const ulonglong2 wv = *reinterpret_cast<const ulonglong2*>(aW2P + (k4*32 + lane)*4);
        const ulonglong2 sv = *reinterpret_cast<const ulonglong2*>(&scr[e][k4*4]);
        t2a = ffma2(sv.x, wv.x, t2a); t2a = ffma2(sv.y, wv.y, t2a);
      }
      t2 = fmaxf(hsum2(t2a) + ab2[lane], 0.f);
    }
    BAR_ELEM(e);

    if (wh == 1){
      u64 A01 = warpsum2(pack2(t2*aW3[lane*3+0], t2*aW3[lane*3+1]));
      float a2 = warpsum(t2*aW3[lane*3+2]);
      if (lane < 3){
        float v = (lane == 0) ? (lo2(A01) + ab3[0] + 0.1f*physs[e][0])
                : (lane == 1) ? (hi2(A01) + ab3[1] + 0.1f*physs[e][1])
                              : (a2       + ab3[2] + 0.1f*physs[e][2]);
        out[(b*T_STEPS + t)*3 + lane] = v;
      }
    }
    BAR_ELEM(e);   // elem may drift into next step's GAT (own slots only)
  }
}

extern "C" void kernel_launch(void* const* d_in, const int* in_sizes, int n_in,
                              void* d_out, int out_size)
{
  const int off = (n_in >= 30) ? 1 : 0;
  const int*   gesture_idx  = (const int*)  d_in[0];
  const float* demographics = (const float*)d_in[1];
  const float* emb_table = (const float*)d_in[2 + off];
  const float* dW1  = (const float*)d_in[3 + off];
  const float* db1  = (const float*)d_in[4 + off];
  const float* dW2  = (const float*)d_in[5 + off];
  const float* db2  = (const float*)d_in[6 + off];
  const float* jiW  = (const float*)d_in[7 + off];
  const float* jib  = (const float*)d_in[8 + off];
  const float* gatW = (const float*)d_in[9 + off];
  const float* gat_asrc = (const float*)d_in[10 + off];
  const float* gat_adst = (const float*)d_in[11 + off];
  const float* gat_b    = (const float*)d_in[12 + off];
  const float* ln_g = (const float*)d_in[13 + off];
  const float* ln_b = (const float*)d_in[14 + off];
  const float* W_ih = (const float*)d_in[15 + off];
  const float* W_hh = (const float*)d_in[16 + off];
  const float* b_ih = (const float*)d_in[17 + off];
  const float* b_hh = (const float*)d_in[18 + off];
  const float* pW1  = (const float*)d_in[19 + off];
  const float* pb1  = (const float*)d_in[20 + off];
  const float* pW2  = (const float*)d_in[21 + off];
  const float* pb2  = (const float*)d_in[22 + off];
  const float* aW1  = (const float*)d_in[23 + off];
  const float* ab1  = (const float*)d_in[24 + off];
  const float* aW2  = (const float*)d_in[25 + off];
  const float* ab2  = (const float*)d_in[26 + off];
  const float* aW3  = (const float*)d_in[27 + off];
  const float* ab3  = (const float*)d_in[28 + off];

  repack_kernel<<<128, 256>>>(gatW, W_ih, W_hh, pW1, aW1, aW2, b_ih, b_hh);
  vkc_kernel<<<256, 256>>>(gesture_idx, demographics, emb_table,
                           dW1, db1, dW2, db2, jiW, jib,
                           gat_asrc, gat_adst, gat_b, ln_g, ln_b,
                           pb1, pW2, pb2,
                           ab1, ab2,
                           aW3, ab3,
                           (float*)d_out);
}

// round 16
// speedup vs baseline: 1.4184x; 1.0125x over previous
#include <cuda_runtime.h>
#include <cstdint>

#define T_STEPS 64
typedef unsigned long long u64;

// ---------------- packed f32x2 helpers ----------------
__device__ __forceinline__ u64 ffma2(u64 a, u64 b, u64 c){
  u64 d; asm("fma.rn.f32x2 %0, %1, %2, %3;" : "=l"(d) : "l"(a), "l"(b), "l"(c)); return d;
}
__device__ __forceinline__ u64 addf2(u64 a, u64 b){
  u64 d; asm("add.rn.f32x2 %0, %1, %2;" : "=l"(d) : "l"(a), "l"(b)); return d;
}
__device__ __forceinline__ u64 pack2(float lo, float hi){
  u64 d; asm("mov.b64 %0, {%1, %2};" : "=l"(d) : "f"(lo), "f"(hi)); return d;
}
__device__ __forceinline__ float lo2(u64 a){ return __uint_as_float((unsigned)a); }
__device__ __forceinline__ float hi2(u64 a){ return __uint_as_float((unsigned)(a >> 32)); }
__device__ __forceinline__ float hsum2(u64 a){ return lo2(a) + hi2(a); }
__device__ __forceinline__ float rcpa(float x){
  float r; asm("rcp.approx.f32 %0, %1;" : "=f"(r) : "f"(x)); return r;
}

#define BAR_ELEM(e) asm volatile("bar.sync %0, 64;" :: "r"((e)+1) : "memory")

// ---------------- repacked weights (loop-invariant, built by pre-kernel) ----------------
__device__ __align__(16) float gatP[49152];   // [l][k4][c][4] : gatW[l][4k4+i][c]
__device__ __align__(16) float WihP[65536];   // [k4][c][4]
__device__ __align__(16) float WhhP[65536];
__device__ __align__(16) float pW1P[8192];
__device__ __align__(16) float aW1P[8192];
__device__ __align__(16) float aW2P[2048];
__device__ __align__(16) float bsumP[512];    // b_ih + b_hh

__global__ void repack_kernel(const float* __restrict__ gatW, const float* __restrict__ W_ih,
                              const float* __restrict__ W_hh, const float* __restrict__ pW1,
                              const float* __restrict__ aW1,  const float* __restrict__ aW2,
                              const float* __restrict__ b_ih, const float* __restrict__ b_hh){
  for (int idx = blockIdx.x*blockDim.x + threadIdx.x; idx < 199168; idx += gridDim.x*blockDim.x){
    if (idx < 49152){
      int f = idx; int i = f&3, c = (f>>2)&127, k4 = (f>>9)&31, l = f>>14;
      gatP[f] = gatW[(l*128 + k4*4 + i)*128 + c];
    } else if (idx < 114688){
      int f = idx - 49152; int i = f&3, c = (f>>2)&511, k4 = f>>11;
      WihP[f] = W_ih[(k4*4+i)*512 + c];
    } else if (idx < 180224){
      int f = idx - 114688; int i = f&3, c = (f>>2)&511, k4 = f>>11;
      WhhP[f] = W_hh[(k4*4+i)*512 + c];
    } else if (idx < 188416){
      int f = idx - 180224; int i = f&3, c = (f>>2)&63, k4 = f>>8;
      pW1P[f] = pW1[(k4*4+i)*64 + c];
    } else if (idx < 196608){
      int f = idx - 188416; int i = f&3, c = (f>>2)&63, k4 = f>>8;
      aW1P[f] = aW1[(k4*4+i)*64 + c];
    } else if (idx < 198656){
      int f = idx - 196608; int i = f&3, c = (f>>2)&31, k4 = f>>7;
      aW2P[f] = aW2[(k4*4+i)*32 + c];
    } else {
      int f = idx - 198656;
      bsumP[f] = b_ih[f] + b_hh[f];
    }
  }
}

// ---------------- threefry2x32 (exact JAX, partitionable path) ----------------
__device__ __forceinline__ uint32_t rotl32(uint32_t x, int d){ return __funnelshift_l(x, x, d); }

__device__ __forceinline__ void threefry(uint32_t k0, uint32_t k1, uint32_t x0, uint32_t x1,
                                         uint32_t& o0, uint32_t& o1){
  uint32_t k2 = k0 ^ k1 ^ 0x1BD11BDAu;
  x0 += k0; x1 += k1;
  #define TFR(a,b,c,d) \
    x0 += x1; x1 = rotl32(x1,a); x1 ^= x0; \
    x0 += x1; x1 = rotl32(x1,b); x1 ^= x0; \
    x0 += x1; x1 = rotl32(x1,c); x1 ^= x0; \
    x0 += x1; x1 = rotl32(x1,d); x1 ^= x0;
  TFR(13,15,26,6)  x0 += k1; x1 += k2 + 1u;
  TFR(17,29,16,24) x0 += k2; x1 += k0 + 2u;
  TFR(13,15,26,6)  x0 += k0; x1 += k1 + 3u;
  TFR(17,29,16,24) x0 += k1; x1 += k2 + 4u;
  TFR(13,15,26,6)  x0 += k2; x1 += k0 + 5u;
  #undef TFR
  o0 = x0; o1 = x1;
}

// XLA ErfInv f32 (Giles polynomial)
__device__ __forceinline__ float erfinv_f(float x){
  float w = -__logf(fmaf(-x, x, 1.0f));
  float p;
  if (w < 5.0f){
    w -= 2.5f;
    p = 2.81022636e-08f;
    p = fmaf(p, w, 3.43273939e-07f);
    p = fmaf(p, w, -3.5233877e-06f);
    p = fmaf(p, w, -4.39150654e-06f);
    p = fmaf(p, w, 0.00021858087f);
    p = fmaf(p, w, -0.00125372503f);
    p = fmaf(p, w, -0.00417768164f);
    p = fmaf(p, w, 0.246640727f);
    p = fmaf(p, w, 1.50140941f);
  } else {
    w = sqrtf(w) - 3.0f;
    p = -0.000200214257f;
    p = fmaf(p, w, 0.000100950558f);
    p = fmaf(p, w, 0.00134934322f);
    p = fmaf(p, w, -0.00367342844f);
    p = fmaf(p, w, 0.00573950773f);
    p = fmaf(p, w, -0.0076224613f);
    p = fmaf(p, w, 0.00943887047f);
    p = fmaf(p, w, 1.00167406f);
    p = fmaf(p, w, 2.83297682f);
  }
  return p * x;
}

__device__ __forceinline__ float bits_to_normal(uint32_t bits){
  float f = __uint_as_float((bits >> 9) | 0x3f800000u) - 1.0f;
  const float lo = -0.99999994f;
  float u = fmaf(f, 2.0f, lo);
  u = fmaxf(u, lo);
  return 1.41421356237309515f * erfinv_f(u);
}

__device__ __forceinline__ float warpsum(float v){
  #pragma unroll
  for (int o = 16; o > 0; o >>= 1) v += __shfl_xor_sync(0xffffffffu, v, o);
  return v;
}
__device__ __forceinline__ u64 warpsum2(u64 v){
  #pragma unroll
  for (int o = 16; o > 0; o >>= 1){
    uint32_t l = (uint32_t)v, h = (uint32_t)(v >> 32);
    l = __shfl_xor_sync(0xffffffffu, l, o);
    h = __shfl_xor_sync(0xffffffffu, h, o);
    v = addf2(v, ((u64)h << 32) | l);
  }
  return v;
}
__device__ __forceinline__ float sig_(float x){ return rcpa(1.0f + __expf(-x)); }
__device__ __forceinline__ float tanh_(float x){ return fmaf(2.0f, rcpa(1.0f + __expf(-2.0f*x)), -1.0f); }
__device__ __forceinline__ float leaky_(float x){ return x > 0.f ? x : 0.2f*x; }

// ------- mega kernel: 1 block = 7 batch elems, 2 warps/elem (+1 spare pair), 1 CTA/SM -------
__global__ __launch_bounds__(512, 1)
void vkc_kernel(
  const int*   __restrict__ gesture_idx,
  const float* __restrict__ demographics,
  const float* __restrict__ emb_table,
  const float* __restrict__ dW1, const float* __restrict__ db1,
  const float* __restrict__ dW2, const float* __restrict__ db2,
  const float* __restrict__ jiW, const float* __restrict__ jib,
  const float* __restrict__ gat_asrc,
  const float* __restrict__ gat_adst, const float* __restrict__ gat_b,
  const float* __restrict__ ln_g, const float* __restrict__ ln_b,
  const float* __restrict__ pb1,
  const float* __restrict__ pW2, const float* __restrict__ pb2,
  const float* __restrict__ ab1,
  const float* __restrict__ ab2,
  const float* __restrict__ aW3, const float* __restrict__ ab3,
  float* __restrict__ out)
{
  __shared__ __align__(16) float xs[21][128];     // x state: 7 elems x 3 joints
  __shared__ __align__(16) float gates[7][512];   // also comb[7][256] in setup
  __shared__ __align__(16) float hs[7][128];
  __shared__ __align__(16) float cs[7][128];
  __shared__ __align__(16) float scr[7][64];
  __shared__ __align__(16) u64   statU[7][6];     // LN partials: [e][wh*3 + row]
  __shared__              float physs[7][3];

  const int tid  = threadIdx.x;
  const int w    = tid >> 5;     // warp 0..15
  const int lane = tid & 31;
  const int e    = w >> 1;       // local element 0..7 (7 = spare)
  const int wh   = w & 1;        // warp-half within element
  const bool act = (e < 7);
  const int g    = blockIdx.x;   // 0..146
  const int bRaw = g*7 + e;
  const int b    = (bRaw < 1024) ? bRaw : 1023;   // clamp; dup elems compute identical values
  const int wr   = e * 3;        // row base in xs
  const int c0   = wh*32 + lane; // first col (head wh)
  const int c1   = c0 + 64;      // second col (head wh+2)
  float* const gtE = gates[(e < 7) ? e : 0];

  // ---------------- setup: demo MLP + embedding -> combined ----------------
  if (act){
    float dm[7];
    #pragma unroll
    for (int i = 0; i < 7; i++) dm[i] = demographics[b*7 + i];
    float a0 = db1[c0];
    #pragma unroll
    for (int i = 0; i < 7; i++) a0 = fmaf(dm[i], dW1[i*64 + c0], a0);
    scr[e][c0] = fmaxf(a0, 0.f);
  }
  __syncthreads();
  if (act){
    const int gi = gesture_idx[b];
    #pragma unroll
    for (int q = 0; q < 2; q++){
      int c = wh*64 + 32*q + lane;
      gtE[c] = emb_table[gi*128 + c];
      float acc = db2[c];
      #pragma unroll 4
      for (int k = 0; k < 64; k++) acc = fmaf(scr[e][k], dW2[k*128 + c], acc);
      gtE[128 + c] = acc;
      hs[e][c] = 0.f; cs[e][c] = 0.f;
    }
  }
  __syncthreads();

  // ---------------- jf = relu(combined @ jiW + jib) -> xs (per elem) ----------------
  if (act){
    float acc[6];
    #pragma unroll
    for (int i = 0; i < 6; i++) acc[i] = 0.f;
    #pragma unroll 4
    for (int k = 0; k < 256; k++){
      float cv = gtE[k];
      #pragma unroll
      for (int j = 0; j < 3; j++){
        acc[j]   = fmaf(cv, jiW[j*32768 + k*128 + c0], acc[j]);
        acc[3+j] = fmaf(cv, jiW[j*32768 + k*128 + c1], acc[3+j]);
      }
    }
    #pragma unroll
    for (int j = 0; j < 3; j++){
      xs[wr+j][c0] = fmaxf(acc[j]   + jib[j*128 + c0], 0.f);
      xs[wr+j][c1] = fmaxf(acc[3+j] + jib[j*128 + c1], 0.f);
    }
  }
  __syncthreads();

  // ---------------- time loop ----------------
  for (int t = 0; t < T_STEPS; t++){
    // ===== 3 GAT layers (register-resident; elem-local, warps 14/15 skip) =====
    if (act){
      #pragma unroll 1
      for (int l = 0; l < 3; l++){
        u64 acc[6];
        #pragma unroll
        for (int i = 0; i < 6; i++) acc[i] = 0ull;
        {
          const float* Wl = gatP + l*16384;
          #pragma unroll 4
          for (int k4 = 0; k4 < 32; k4++){
            const ulonglong2 wv0 = *reinterpret_cast<const ulonglong2*>(Wl + (k4*128 + c0)*4);
            const ulonglong2 wv1 = *reinterpret_cast<const ulonglong2*>(Wl + (k4*128 + c1)*4);
            #pragma unroll
            for (int r = 0; r < 3; r++){
              const ulonglong2 xv = *reinterpret_cast<const ulonglong2*>(&xs[wr + r][k4*4]);
              acc[r*2+0] = ffma2(xv.x, wv0.x, acc[r*2+0]);
              acc[r*2+0] = ffma2(xv.y, wv0.y, acc[r*2+0]);
              acc[r*2+1] = ffma2(xv.x, wv1.x, acc[r*2+1]);
              acc[r*2+1] = ffma2(xv.y, wv1.y, acc[r*2+1]);
            }
          }
        }
        float x0a = hsum2(acc[0]), x0b = hsum2(acc[1]);
        float x1a = hsum2(acc[2]), x1b = hsum2(acc[3]);
        float x2a = hsum2(acc[4]), x2b = hsum2(acc[5]);

        // attention dots (packed: lo=head wh, hi=head wh+2)
        float v0a, v1a, v2a, v0b, v1b, v2b;
        {
          const float asa = gat_asrc[l*128 + c0], asb = gat_asrc[l*128 + c1];
          const float ada = gat_adst[l*128 + c0], adb = gat_adst[l*128 + c1];
          u64 S0 = warpsum2(pack2(x0a*asa, x0b*asb));
          u64 S1 = warpsum2(pack2(x1a*asa, x1b*asb));
          u64 S2 = warpsum2(pack2(x2a*asa, x2b*asb));
          u64 D1 = warpsum2(pack2(x1a*ada, x1b*adb));
          u64 D2 = warpsum2(pack2(x2a*ada, x2b*adb));
          {
            float e10 = leaky_(lo2(D1)+lo2(S0)), e11 = leaky_(lo2(D1)+lo2(S1));
            float e21 = leaky_(lo2(D2)+lo2(S1)), e22 = leaky_(lo2(D2)+lo2(S2));
            float m1 = fmaxf(e10, e11);
            float p10 = __expf(e10-m1), p11 = __expf(e11-m1);
            float i1 = rcpa(p10+p11);
            float m2 = fmaxf(e21, e22);
            float p21 = __expf(e21-m2), p22 = __expf(e22-m2);
            float i2 = rcpa(p21+p22);
            v0a = x0a;
            v1a = (p10*x0a + p11*x1a)*i1;
            v2a = (p21*x1a + p22*x2a)*i2;
          }
          {
            float e10 = leaky_(hi2(D1)+hi2(S0)), e11 = leaky_(hi2(D1)+hi2(S1));
            float e21 = leaky_(hi2(D2)+hi2(S1)), e22 = leaky_(hi2(D2)+hi2(S2));
            float m1 = fmaxf(e10, e11);
            float p10 = __expf(e10-m1), p11 = __expf(e11-m1);
            float i1 = rcpa(p10+p11);
            float m2 = fmaxf(e21, e22);
            float p21 = __expf(e21-m2), p22 = __expf(e22-m2);
            float i2 = rcpa(p21+p22);
            v0b = x0b;
            v1b = (p10*x0b + p11*x1b)*i1;
            v2b = (p21*x1b + p22*x2b)*i2;
          }
        }

        // bias + LN stats (both warps all 3 rows; cross-warp exchange via statU)
        {
          const float gba = gat_b[l*128 + c0], gbb = gat_b[l*128 + c1];
          v0a += gba; v0b += gbb;
          v1a += gba; v1b += gbb;
          v2a += gba; v2b += gbb;
          u64 R0 = warpsum2(pack2(v0a + v0b, fmaf(v0a, v0a, v0b*v0b)));
          u64 R1 = warpsum2(pack2(v1a + v1b, fmaf(v1a, v1a, v1b*v1b)));
          u64 R2 = warpsum2(pack2(v2a + v2b, fmaf(v2a, v2a, v2b*v2b)));
          if (lane == 0){
            statU[e][wh*3 + 0] = R0;
            statU[e][wh*3 + 1] = R1;
            statU[e][wh*3 + 2] = R2;
          }
          BAR_ELEM(e);
          const int ow = (1 - wh)*3;
          u64 T0 = addf2(R0, statU[e][ow + 0]);
          u64 T1 = addf2(R1, statU[e][ow + 1]);
          u64 T2 = addf2(R2, statU[e][ow + 2]);
          const float lga = ln_g[l*128 + c0], lgb = ln_g[l*128 + c1];
          const float lba = ln_b[l*128 + c0], lbb = ln_b[l*128 + c1];
          float mu, inv;
          #define LN_ROW(Tr, va, vb, row)                                        \
          {                                                                      \
            mu  = lo2(Tr) * (1.f/128.f);                                         \
            float var = fmaf(-mu, mu, hi2(Tr) * (1.f/128.f));                    \
            inv = rsqrtf(var + 1e-5f);                                           \
            float ya = fmaf((va - mu)*inv, lga, lba);                            \
            float yb = fmaf((vb - mu)*inv, lgb, lbb);                            \
            xs[wr + row][c0] = fmaxf(ya, 0.f) + xs[wr + row][c0];                \
            xs[wr + row][c1] = fmaxf(yb, 0.f) + xs[wr + row][c1];                \
          }
          LN_ROW(T0, v0a, v0b, 0)
          LN_ROW(T1, v1a, v1b, 1)
          LN_ROW(T2, v2a, v2b, 2)
          #undef LN_ROW
        }
        BAR_ELEM(e);   // xs ready for next layer (elem-local)
      }
    }
    __syncthreads();   // all elems' xs row2 + hs ready for block-wide LSTM GEMM

    // ===== LSTM gates GEMM (all 512 threads): 1 col x 7 elems per thread =====
    {
      const int c = tid;                 // 0..511
      u64 acc[7];
      #pragma unroll
      for (int ee = 0; ee < 7; ee++) acc[ee] = pack2(bsumP[c], 0.f);
      #pragma unroll 2
      for (int k4 = 0; k4 < 32; k4++){
        const ulonglong2 wi  = *reinterpret_cast<const ulonglong2*>(WihP + (k4*512 + c)*4);
        const ulonglong2 wo  = *reinterpret_cast<const ulonglong2*>(WhhP + (k4*512 + c)*4);
        #pragma unroll
        for (int ee = 0; ee < 7; ee++){
          const ulonglong2 xv = *reinterpret_cast<const ulonglong2*>(&xs[ee*3+2][k4*4]);
          const ulonglong2 hv = *reinterpret_cast<const ulonglong2*>(&hs[ee][k4*4]);
          u64 a = acc[ee];
          a = ffma2(xv.x, wi.x, a); a = ffma2(xv.y, wi.y, a);
          a = ffma2(hv.x, wo.x, a); a = ffma2(hv.y, wo.y, a);
          acc[ee] = a;
        }
      }
      #pragma unroll
      for (int ee = 0; ee < 7; ee++) gates[ee][c] = hsum2(acc[ee]);
    }
    __syncthreads();

    if (act){
      // ===== LSTM pointwise (elem warps; bias folded in) =====
      #pragma unroll
      for (int qq = 0; qq < 2; qq++){
        int cx = lane + 32*(2*wh + qq);
        float gi = gtE[cx];
        float gf = gtE[128 + cx];
        float gg = gtE[256 + cx];
        float go = gtE[384 + cx];
        float cn = sig_(gf)*cs[e][cx] + sig_(gi)*tanh_(gg);
        float hn = sig_(go)*tanh_(cn);
        cs[e][cx] = cn; hs[e][cx] = hn;
      }

      // ===== noise (elem-local): x += 0.05 * normal * (t/64); skip t=0 and t=63 =====
      if (t >= 1 && t < T_STEPS - 1){
        const float scale = 0.05f * (float)t * (1.0f/64.0f);
        uint32_t kt0, kt1;
        threefry(0u, 42u, 0u, (uint32_t)t, kt0, kt1);
        #pragma unroll 1
        for (int ii = wh*32 + lane; ii < 384; ii += 64){
          uint32_t m = (uint32_t)(b*384 + ii);
          uint32_t o0, o1;
          threefry(kt0, kt1, 0u, m, o0, o1);
          xs[wr + (ii >> 7)][ii & 127] += scale * bits_to_normal(o0 ^ o1);
        }
      }
      BAR_ELEM(e);   // hs + noised xs complete within element

      // ===== output heads: wh0 = phys path, wh1 = act path =====
      float t2 = 0.f;
      if (wh == 0){
        u64 pa = 0ull, pb = 0ull;
        #pragma unroll 4
        for (int k4 = 0; k4 < 32; k4++){
          const ulonglong2 wA = *reinterpret_cast<const ulonglong2*>(pW1P + (k4*64 + lane   )*4);
          const ulonglong2 wB = *reinterpret_cast<const ulonglong2*>(pW1P + (k4*64 + lane+32)*4);
          const ulonglong2 hv = *reinterpret_cast<const ulonglong2*>(&hs[e][k4*4]);
          pa = ffma2(hv.x, wA.x, pa); pa = ffma2(hv.y, wA.y, pa);
          pb = ffma2(hv.x, wB.x, pb); pb = ffma2(hv.y, wB.y, pb);
        }
        float p_a = fmaxf(hsum2(pa) + pb1[lane],    0.f);
        float p_b = fmaxf(hsum2(pb) + pb1[lane+32], 0.f);
        u64 P01 = warpsum2(pack2(p_a*pW2[lane*3+0] + p_b*pW2[(lane+32)*3+0],
                                 p_a*pW2[lane*3+1] + p_b*pW2[(lane+32)*3+1]));
        float ph2 = warpsum(p_a*pW2[lane*3+2] + p_b*pW2[(lane+32)*3+2]);
        if (lane == 0){
          physs[e][0] = lo2(P01) + pb2[0];
          physs[e][1] = hi2(P01) + pb2[1];
          physs[e][2] = ph2      + pb2[2];
        }
      } else {
        u64 aa = 0ull, ab = 0ull;
        #pragma unroll 4
        for (int k4 = 0; k4 < 32; k4++){
          const ulonglong2 wA = *reinterpret_cast<const ulonglong2*>(aW1P + (k4*64 + lane   )*4);
          const ulonglong2 wB = *reinterpret_cast<const ulonglong2*>(aW1P + (k4*64 + lane+32)*4);
          const ulonglong2 hv = *reinterpret_cast<const ulonglong2*>(&hs[e][k4*4]);
          aa = ffma2(hv.x, wA.x, aa); aa = ffma2(hv.y, wA.y, aa);
          ab = ffma2(hv.x, wB.x, ab); ab = ffma2(hv.y, wB.y, ab);
        }
        scr[e][lane]    = fmaxf(hsum2(aa) + ab1[lane],    0.f);
        scr[e][lane+32] = fmaxf(hsum2(ab) + ab1[lane+32], 0.f);
        __syncwarp();
        u64 t2a = 0ull;
        #pragma unroll
        for (int k4 = 0; k4 < 16; k4++){
          const ulonglong2 wv = *reinterpret_cast<const ulonglong2*>(aW2P + (k4*32 + lane)*4);
          const ulonglong2 sv = *reinterpret_cast<const ulonglong2*>(&scr[e][k4*4]);
          t2a = ffma2(sv.x, wv.x, t2a); t2a = ffma2(sv.y, wv.y, t2a);
        }
        t2 = fmaxf(hsum2(t2a) + ab2[lane], 0.f);
      }
      BAR_ELEM(e);

      if (wh == 1){
        u64 A01 = warpsum2(pack2(t2*aW3[lane*3+0], t2*aW3[lane*3+1]));
        float a2 = warpsum(t2*aW3[lane*3+2]);
        if (bRaw < 1024 && lane < 3){
          float v = (lane == 0) ? (lo2(A01) + ab3[0] + 0.1f*physs[e][0])
                  : (lane == 1) ? (hi2(A01) + ab3[1] + 0.1f*physs[e][1])
                                : (a2       + ab3[2] + 0.1f*physs[e][2]);
          out[(b*T_STEPS + t)*3 + lane] = v;
        }
      }
      // no trailing barrier: physs WAR is covered by the LN-exchange BAR next layer,
      // and xs/gates accesses are ordered by the block-wide __syncthreads.
    }
  }
}

extern "C" void kernel_launch(void* const* d_in, const int* in_sizes, int n_in,
                              void* d_out, int out_size)
{
  const int off = (n_in >= 30) ? 1 : 0;
  const int*   gesture_idx  = (const int*)  d_in[0];
  const float* demographics = (const float*)d_in[1];
  const float* emb_table = (const float*)d_in[2 + off];
  const float* dW1  = (const float*)d_in[3 + off];
  const float* db1  = (const float*)d_in[4 + off];
  const float* dW2  = (const float*)d_in[5 + off];
  const float* db2  = (const float*)d_in[6 + off];
  const float* jiW  = (const float*)d_in[7 + off];
  const float* jib  = (const float*)d_in[8 + off];
  const float* gatW = (const float*)d_in[9 + off];
  const float* gat_asrc = (const float*)d_in[10 + off];
  const float* gat_adst = (const float*)d_in[11 + off];
  const float* gat_b    = (const float*)d_in[12 + off];
  const float* ln_g = (const float*)d_in[13 + off];
  const float* ln_b = (const float*)d_in[14 + off];
  const float* W_ih = (const float*)d_in[15 + off];
  const float* W_hh = (const float*)d_in[16 + off];
  const float* b_ih = (const float*)d_in[17 + off];
  const float* b_hh = (const float*)d_in[18 + off];
  const float* pW1  = (const float*)d_in[19 + off];
  const float* pb1  = (const float*)d_in[20 + off];
  const float* pW2  = (const float*)d_in[21 + off];
  const float* pb2  = (const float*)d_in[22 + off];
  const float* aW1  = (const float*)d_in[23 + off];
  const float* ab1  = (const float*)d_in[24 + off];
  const float* aW2  = (const float*)d_in[25 + off];
  const float* ab2  = (const float*)d_in[26 + off];
  const float* aW3  = (const float*)d_in[27 + off];
  const float* ab3  = (const float*)d_in[28 + off];

  repack_kernel<<<128, 256>>>(gatW, W_ih, W_hh, pW1, aW1, aW2, b_ih, b_hh);
  vkc_kernel<<<147, 512>>>(gesture_idx, demographics, emb_table,
                           dW1, db1, dW2, db2, jiW, jib,
                           gat_asrc, gat_adst, gat_b, ln_g, ln_b,
                           pb1, pW2, pb2,
                           ab1, ab2,
                           aW3, ab3,
                           (float*)d_out);
}

// round 17
// speedup vs baseline: 1.5304x; 1.0789x over previous
#include <cuda_runtime.h>
#include <cstdint>

#define T_STEPS 64
typedef unsigned long long u64;

// ---------------- packed f32x2 helpers ----------------
__device__ __forceinline__ u64 ffma2(u64 a, u64 b, u64 c){
  u64 d; asm("fma.rn.f32x2 %0, %1, %2, %3;" : "=l"(d) : "l"(a), "l"(b), "l"(c)); return d;
}
__device__ __forceinline__ u64 addf2(u64 a, u64 b){
  u64 d; asm("add.rn.f32x2 %0, %1, %2;" : "=l"(d) : "l"(a), "l"(b)); return d;
}
__device__ __forceinline__ u64 pack2(float lo, float hi){
  u64 d; asm("mov.b64 %0, {%1, %2};" : "=l"(d) : "f"(lo), "f"(hi)); return d;
}
__device__ __forceinline__ float lo2(u64 a){ return __uint_as_float((unsigned)a); }
__device__ __forceinline__ float hi2(u64 a){ return __uint_as_float((unsigned)(a >> 32)); }
__device__ __forceinline__ float hsum2(u64 a){ return lo2(a) + hi2(a); }
__device__ __forceinline__ float rcpa(float x){
  float r; asm("rcp.approx.f32 %0, %1;" : "=f"(r) : "f"(x)); return r;
}

#define BAR_ELEM(e) asm volatile("bar.sync %0, 64;" :: "r"((e)+1) : "memory")

// ---------------- repacked weights (loop-invariant, built by pre-kernel) ----------------
__device__ __align__(16) float gatP[49152];   // [l][k4][c][4] : gatW[l][4k4+i][c]
__device__ __align__(16) float WihP[65536];   // [k4][c][4]
__device__ __align__(16) float WhhP[65536];
__device__ __align__(16) float pW1P[8192];
__device__ __align__(16) float aW1P[8192];
__device__ __align__(16) float aW2P[2048];
__device__ __align__(16) float bsumP[512];    // b_ih + b_hh

__global__ void repack_kernel(const float* __restrict__ gatW, const float* __restrict__ W_ih,
                              const float* __restrict__ W_hh, const float* __restrict__ pW1,
                              const float* __restrict__ aW1,  const float* __restrict__ aW2,
                              const float* __restrict__ b_ih, const float* __restrict__ b_hh){
  for (int idx = blockIdx.x*blockDim.x + threadIdx.x; idx < 199168; idx += gridDim.x*blockDim.x){
    if (idx < 49152){
      int f = idx; int i = f&3, c = (f>>2)&127, k4 = (f>>9)&31, l = f>>14;
      gatP[f] = gatW[(l*128 + k4*4 + i)*128 + c];
    } else if (idx < 114688){
      int f = idx - 49152; int i = f&3, c = (f>>2)&511, k4 = f>>11;
      WihP[f] = W_ih[(k4*4+i)*512 + c];
    } else if (idx < 180224){
      int f = idx - 114688; int i = f&3, c = (f>>2)&511, k4 = f>>11;
      WhhP[f] = W_hh[(k4*4+i)*512 + c];
    } else if (idx < 188416){
      int f = idx - 180224; int i = f&3, c = (f>>2)&63, k4 = f>>8;
      pW1P[f] = pW1[(k4*4+i)*64 + c];
    } else if (idx < 196608){
      int f = idx - 188416; int i = f&3, c = (f>>2)&63, k4 = f>>8;
      aW1P[f] = aW1[(k4*4+i)*64 + c];
    } else if (idx < 198656){
      int f = idx - 196608; int i = f&3, c = (f>>2)&31, k4 = f>>7;
      aW2P[f] = aW2[(k4*4+i)*32 + c];
    } else {
      int f = idx - 198656;
      bsumP[f] = b_ih[f] + b_hh[f];
    }
  }
}

// ---------------- threefry2x32 (exact JAX, partitionable path) ----------------
__device__ __forceinline__ uint32_t rotl32(uint32_t x, int d){ return __funnelshift_l(x, x, d); }

__device__ __forceinline__ void threefry(uint32_t k0, uint32_t k1, uint32_t x0, uint32_t x1,
                                         uint32_t& o0, uint32_t& o1){
  uint32_t k2 = k0 ^ k1 ^ 0x1BD11BDAu;
  x0 += k0; x1 += k1;
  #define TFR(a,b,c,d) \
    x0 += x1; x1 = rotl32(x1,a); x1 ^= x0; \
    x0 += x1; x1 = rotl32(x1,b); x1 ^= x0; \
    x0 += x1; x1 = rotl32(x1,c); x1 ^= x0; \
    x0 += x1; x1 = rotl32(x1,d); x1 ^= x0;
  TFR(13,15,26,6)  x0 += k1; x1 += k2 + 1u;
  TFR(17,29,16,24) x0 += k2; x1 += k0 + 2u;
  TFR(13,15,26,6)  x0 += k0; x1 += k1 + 3u;
  TFR(17,29,16,24) x0 += k1; x1 += k2 + 4u;
  TFR(13,15,26,6)  x0 += k2; x1 += k0 + 5u;
  #undef TFR
  o0 = x0; o1 = x1;
}

// XLA ErfInv f32 (Giles polynomial)
__device__ __forceinline__ float erfinv_f(float x){
  float w = -__logf(fmaf(-x, x, 1.0f));
  float p;
  if (w < 5.0f){
    w -= 2.5f;
    p = 2.81022636e-08f;
    p = fmaf(p, w, 3.43273939e-07f);
    p = fmaf(p, w, -3.5233877e-06f);
    p = fmaf(p, w, -4.39150654e-06f);
    p = fmaf(p, w, 0.00021858087f);
    p = fmaf(p, w, -0.00125372503f);
    p = fmaf(p, w, -0.00417768164f);
    p = fmaf(p, w, 0.246640727f);
    p = fmaf(p, w, 1.50140941f);
  } else {
    w = sqrtf(w) - 3.0f;
    p = -0.000200214257f;
    p = fmaf(p, w, 0.000100950558f);
    p = fmaf(p, w, 0.00134934322f);
    p = fmaf(p, w, -0.00367342844f);
    p = fmaf(p, w, 0.00573950773f);
    p = fmaf(p, w, -0.0076224613f);
    p = fmaf(p, w, 0.00943887047f);
    p = fmaf(p, w, 1.00167406f);
    p = fmaf(p, w, 2.83297682f);
  }
  return p * x;
}

__device__ __forceinline__ float bits_to_normal(uint32_t bits){
  float f = __uint_as_float((bits >> 9) | 0x3f800000u) - 1.0f;
  const float lo = -0.99999994f;
  float u = fmaf(f, 2.0f, lo);
  u = fmaxf(u, lo);
  return 1.41421356237309515f * erfinv_f(u);
}

__device__ __forceinline__ float warpsum(float v){
  #pragma unroll
  for (int o = 16; o > 0; o >>= 1) v += __shfl_xor_sync(0xffffffffu, v, o);
  return v;
}
__device__ __forceinline__ u64 warpsum2(u64 v){
  #pragma unroll
  for (int o = 16; o > 0; o >>= 1){
    uint32_t l = (uint32_t)v, h = (uint32_t)(v >> 32);
    l = __shfl_xor_sync(0xffffffffu, l, o);
    h = __shfl_xor_sync(0xffffffffu, h, o);
    v = addf2(v, ((u64)h << 32) | l);
  }
  return v;
}
__device__ __forceinline__ float sig_(float x){ return rcpa(1.0f + __expf(-x)); }
__device__ __forceinline__ float tanh_(float x){ return fmaf(2.0f, rcpa(1.0f + __expf(-2.0f*x)), -1.0f); }
__device__ __forceinline__ float leaky_(float x){ return x > 0.f ? x : 0.2f*x; }

// LSTM gates GEMM, compile-time element count (keeps accumulators in registers)
template<int NE>
__device__ __forceinline__ void lstm_gemm(int tid, const float (*xs)[128], const float (*hs)[128],
                                          float (*gates)[512]){
  const int c  = tid;
  const int c2 = tid + 256;
  u64 accA[NE], accB[NE];
  #pragma unroll
  for (int ee = 0; ee < NE; ee++){ accA[ee] = pack2(bsumP[c], 0.f); accB[ee] = pack2(bsumP[c2], 0.f); }
  #pragma unroll 2
  for (int k4 = 0; k4 < 32; k4++){
    const ulonglong2 wiA = *reinterpret_cast<const ulonglong2*>(WihP + (k4*512 + c )*4);
    const ulonglong2 wiB = *reinterpret_cast<const ulonglong2*>(WihP + (k4*512 + c2)*4);
    const ulonglong2 whA = *reinterpret_cast<const ulonglong2*>(WhhP + (k4*512 + c )*4);
    const ulonglong2 whB = *reinterpret_cast<const ulonglong2*>(WhhP + (k4*512 + c2)*4);
    #pragma unroll
    for (int ee = 0; ee < NE; ee++){
      const ulonglong2 xv = *reinterpret_cast<const ulonglong2*>(&xs[ee*3+2][k4*4]);
      const ulonglong2 hv = *reinterpret_cast<const ulonglong2*>(&hs[ee][k4*4]);
      u64 a = accA[ee], bb = accB[ee];
      a  = ffma2(xv.x, wiA.x, a );  a  = ffma2(xv.y, wiA.y, a );
      a  = ffma2(hv.x, whA.x, a );  a  = ffma2(hv.y, whA.y, a );
      bb = ffma2(xv.x, wiB.x, bb);  bb = ffma2(xv.y, wiB.y, bb);
      bb = ffma2(hv.x, whB.x, bb);  bb = ffma2(hv.y, whB.y, bb);
      accA[ee] = a; accB[ee] = bb;
    }
  }
  #pragma unroll
  for (int ee = 0; ee < NE; ee++){
    gates[ee][c]  = hsum2(accA[ee]);
    gates[ee][c2] = hsum2(accB[ee]);
  }
}

// ------- mega kernel: CTA<148 = 4 elems, CTA>=148 = 3 elems; pairs to 7 elems/SM -------
__global__ __launch_bounds__(256, 2)
void vkc_kernel(
  const int*   __restrict__ gesture_idx,
  const float* __restrict__ demographics,
  const float* __restrict__ emb_table,
  const float* __restrict__ dW1, const float* __restrict__ db1,
  const float* __restrict__ dW2, const float* __restrict__ db2,
  const float* __restrict__ jiW, const float* __restrict__ jib,
  const float* __restrict__ gat_asrc,
  const float* __restrict__ gat_adst, const float* __restrict__ gat_b,
  const float* __restrict__ ln_g, const float* __restrict__ ln_b,
  const float* __restrict__ pb1,
  const float* __restrict__ pW2, const float* __restrict__ pb2,
  const float* __restrict__ ab1,
  const float* __restrict__ ab2,
  const float* __restrict__ aW3, const float* __restrict__ ab3,
  float* __restrict__ out)
{
  __shared__ __align__(16) float xs[12][128];     // x state: up to 4 elems x 3 joints
  __shared__ __align__(16) float gates[4][512];   // also comb[4][256] in setup
  __shared__ __align__(16) float hs[4][128];
  __shared__ __align__(16) float cs[4][128];
  __shared__ __align__(16) float scr[4][64];
  __shared__ __align__(16) u64   statU[4][6];     // LN partials: [e][wh*3 + row]
  __shared__              float physs[4][3];

  const int tid  = threadIdx.x;
  const int w    = tid >> 5;     // warp 0..7
  const int lane = tid & 31;
  const int e    = w >> 1;       // local element 0..3
  const int wh   = w & 1;        // warp-half within element
  const int g    = blockIdx.x;   // 0..295
  const bool big = (g < 148);
  const int nE   = big ? 4 : 3;
  const int bBase= big ? g*4 : 592 + (g - 148)*3;
  const int bRaw = bBase + e;
  const int b    = (bRaw < 1024) ? bRaw : 1023;   // clamp; dup elems discarded
  const bool act = (e < nE);
  const int wr   = e * 3;        // row base in xs
  const int c0   = wh*32 + lane; // first col (head wh)
  const int c1   = c0 + 64;      // second col (head wh+2)
  float* const gtE = gates[e];

  // ---------------- setup: demo MLP + embedding -> combined ----------------
  if (act){
    float dm[7];
    #pragma unroll
    for (int i = 0; i < 7; i++) dm[i] = demographics[b*7 + i];
    float a0 = db1[c0];
    #pragma unroll
    for (int i = 0; i < 7; i++) a0 = fmaf(dm[i], dW1[i*64 + c0], a0);
    scr[e][c0] = fmaxf(a0, 0.f);
  }
  __syncthreads();
  {
    // all 4 elems initialized (inactive elem mirrors b=1023) so LSTM GEMM reads
    // defined data; its results for inactive elems are discarded.
    const int gi = gesture_idx[b];
    const int es = act ? e : 0;   // scr source for inactive slot: reuse defined row? no — use own
    (void)es;
    #pragma unroll
    for (int q = 0; q < 2; q++){
      int c = wh*64 + 32*q + lane;
      float acc = db2[c];
      if (act){
        gtE[c] = emb_table[gi*128 + c];
        #pragma unroll 4
        for (int k = 0; k < 64; k++) acc = fmaf(scr[e][k], dW2[k*128 + c], acc);
        gtE[128 + c] = acc;
      } else {
        gates[e][c] = 0.f; gates[e][128 + c] = 0.f;
      }
      hs[e][c] = 0.f; cs[e][c] = 0.f;
    }
  }
  __syncthreads();

  // ---------------- jf = relu(combined @ jiW + jib) -> xs (per elem) ----------------
  {
    float acc[6];
    #pragma unroll
    for (int i = 0; i < 6; i++) acc[i] = 0.f;
    if (act){
      #pragma unroll 4
      for (int k = 0; k < 256; k++){
        float cv = gtE[k];
        #pragma unroll
        for (int j = 0; j < 3; j++){
          acc[j]   = fmaf(cv, jiW[j*32768 + k*128 + c0], acc[j]);
          acc[3+j] = fmaf(cv, jiW[j*32768 + k*128 + c1], acc[3+j]);
        }
      }
    }
    #pragma unroll
    for (int j = 0; j < 3; j++){
      xs[wr+j][c0] = act ? fmaxf(acc[j]   + jib[j*128 + c0], 0.f) : 0.f;
      xs[wr+j][c1] = act ? fmaxf(acc[3+j] + jib[j*128 + c1], 0.f) : 0.f;
    }
  }
  __syncthreads();

  // ---------------- time loop ----------------
  for (int t = 0; t < T_STEPS; t++){
    // ===== 3 GAT layers (register-resident; elem-local) =====
    if (act){
      #pragma unroll 1
      for (int l = 0; l < 3; l++){
        u64 acc[6];
        #pragma unroll
        for (int i = 0; i < 6; i++) acc[i] = 0ull;
        {
          const float* Wl = gatP + l*16384;
          #pragma unroll 4
          for (int k4 = 0; k4 < 32; k4++){
            const ulonglong2 wv0 = *reinterpret_cast<const ulonglong2*>(Wl + (k4*128 + c0)*4);
            const ulonglong2 wv1 = *reinterpret_cast<const ulonglong2*>(Wl + (k4*128 + c1)*4);
            #pragma unroll
            for (int r = 0; r < 3; r++){
              const ulonglong2 xv = *reinterpret_cast<const ulonglong2*>(&xs[wr + r][k4*4]);
              acc[r*2+0] = ffma2(xv.x, wv0.x, acc[r*2+0]);
              acc[r*2+0] = ffma2(xv.y, wv0.y, acc[r*2+0]);
              acc[r*2+1] = ffma2(xv.x, wv1.x, acc[r*2+1]);
              acc[r*2+1] = ffma2(xv.y, wv1.y, acc[r*2+1]);
            }
          }
        }
        float x0a = hsum2(acc[0]), x0b = hsum2(acc[1]);
        float x1a = hsum2(acc[2]), x1b = hsum2(acc[3]);
        float x2a = hsum2(acc[4]), x2b = hsum2(acc[5]);

        // attention dots (packed: lo=head wh, hi=head wh+2)
        float v0a, v1a, v2a, v0b, v1b, v2b;
        {
          const float asa = gat_asrc[l*128 + c0], asb = gat_asrc[l*128 + c1];
          const float ada = gat_adst[l*128 + c0], adb = gat_adst[l*128 + c1];
          u64 S0 = warpsum2(pack2(x0a*asa, x0b*asb));
          u64 S1 = warpsum2(pack2(x1a*asa, x1b*asb));
          u64 S2 = warpsum2(pack2(x2a*asa, x2b*asb));
          u64 D1 = warpsum2(pack2(x1a*ada, x1b*adb));
          u64 D2 = warpsum2(pack2(x2a*ada, x2b*adb));
          {
            float e10 = leaky_(lo2(D1)+lo2(S0)), e11 = leaky_(lo2(D1)+lo2(S1));
            float e21 = leaky_(lo2(D2)+lo2(S1)), e22 = leaky_(lo2(D2)+lo2(S2));
            float m1 = fmaxf(e10, e11);
            float p10 = __expf(e10-m1), p11 = __expf(e11-m1);
            float i1 = rcpa(p10+p11);
            float m2 = fmaxf(e21, e22);
            float p21 = __expf(e21-m2), p22 = __expf(e22-m2);
            float i2 = rcpa(p21+p22);
            v0a = x0a;
            v1a = (p10*x0a + p11*x1a)*i1;
            v2a = (p21*x1a + p22*x2a)*i2;
          }
          {
            float e10 = leaky_(hi2(D1)+hi2(S0)), e11 = leaky_(hi2(D1)+hi2(S1));
            float e21 = leaky_(hi2(D2)+hi2(S1)), e22 = leaky_(hi2(D2)+hi2(S2));
            float m1 = fmaxf(e10, e11);
            float p10 = __expf(e10-m1), p11 = __expf(e11-m1);
            float i1 = rcpa(p10+p11);
            float m2 = fmaxf(e21, e22);
            float p21 = __expf(e21-m2), p22 = __expf(e22-m2);
            float i2 = rcpa(p21+p22);
            v0b = x0b;
            v1b = (p10*x0b + p11*x1b)*i1;
            v2b = (p21*x1b + p22*x2b)*i2;
          }
        }

        // bias + LN stats (both warps all 3 rows; cross-warp exchange via statU)
        {
          const float gba = gat_b[l*128 + c0], gbb = gat_b[l*128 + c1];
          v0a += gba; v0b += gbb;
          v1a += gba; v1b += gbb;
          v2a += gba; v2b += gbb;
          u64 R0 = warpsum2(pack2(v0a + v0b, fmaf(v0a, v0a, v0b*v0b)));
          u64 R1 = warpsum2(pack2(v1a + v1b, fmaf(v1a, v1a, v1b*v1b)));
          u64 R2 = warpsum2(pack2(v2a + v2b, fmaf(v2a, v2a, v2b*v2b)));
          if (lane == 0){
            statU[e][wh*3 + 0] = R0;
            statU[e][wh*3 + 1] = R1;
            statU[e][wh*3 + 2] = R2;
          }
          BAR_ELEM(e);
          const int ow = (1 - wh)*3;
          u64 T0 = addf2(R0, statU[e][ow + 0]);
          u64 T1 = addf2(R1, statU[e][ow + 1]);
          u64 T2 = addf2(R2, statU[e][ow + 2]);
          const float lga = ln_g[l*128 + c0], lgb = ln_g[l*128 + c1];
          const float lba = ln_b[l*128 + c0], lbb = ln_b[l*128 + c1];
          float mu, inv;
          #define LN_ROW(Tr, va, vb, row)                                        \
          {                                                                      \
            mu  = lo2(Tr) * (1.f/128.f);                                         \
            float var = fmaf(-mu, mu, hi2(Tr) * (1.f/128.f));                    \
            inv = rsqrtf(var + 1e-5f);                                           \
            float ya = fmaf((va - mu)*inv, lga, lba);                            \
            float yb = fmaf((vb - mu)*inv, lgb, lbb);                            \
            xs[wr + row][c0] = fmaxf(ya, 0.f) + xs[wr + row][c0];                \
            xs[wr + row][c1] = fmaxf(yb, 0.f) + xs[wr + row][c1];                \
          }
          LN_ROW(T0, v0a, v0b, 0)
          LN_ROW(T1, v1a, v1b, 1)
          LN_ROW(T2, v2a, v2b, 2)
          #undef LN_ROW
        }
        BAR_ELEM(e);   // xs ready for next layer (elem-local)
      }
    }
    __syncthreads();   // all elems' xs row2 + hs ready for block-wide LSTM GEMM

    // ===== LSTM gates GEMM (all 256 threads) =====
    if (big) lstm_gemm<4>(tid, xs, hs, gates);
    else     lstm_gemm<3>(tid, xs, hs, gates);
    __syncthreads();

    if (act){
      // ===== LSTM pointwise (elem warps; bias folded in) =====
      #pragma unroll
      for (int qq = 0; qq < 2; qq++){
        int cx = lane + 32*(2*wh + qq);
        float gi = gtE[cx];
        float gf = gtE[128 + cx];
        float gg = gtE[256 + cx];
        float go = gtE[384 + cx];
        float cn = sig_(gf)*cs[e][cx] + sig_(gi)*tanh_(gg);
        float hn = sig_(go)*tanh_(cn);
        cs[e][cx] = cn; hs[e][cx] = hn;
      }

      // ===== noise (elem-local): x += 0.05 * normal * (t/64); skip t=0 and t=63 =====
      if (t >= 1 && t < T_STEPS - 1){
        const float scale = 0.05f * (float)t * (1.0f/64.0f);
        uint32_t kt0, kt1;
        threefry(0u, 42u, 0u, (uint32_t)t, kt0, kt1);
        #pragma unroll 1
        for (int ii = wh*32 + lane; ii < 384; ii += 64){
          uint32_t m = (uint32_t)(b*384 + ii);
          uint32_t o0, o1;
          threefry(kt0, kt1, 0u, m, o0, o1);
          xs[wr + (ii >> 7)][ii & 127] += scale * bits_to_normal(o0 ^ o1);
        }
      }
      BAR_ELEM(e);   // hs + noised xs complete within element

      // ===== output heads: wh0 = phys path, wh1 = act path =====
      float t2 = 0.f;
      if (wh == 0){
        u64 pa = 0ull, pb = 0ull;
        #pragma unroll 4
        for (int k4 = 0; k4 < 32; k4++){
          const ulonglong2 wA = *reinterpret_cast<const ulonglong2*>(pW1P + (k4*64 + lane   )*4);
          const ulonglong2 wB = *reinterpret_cast<const ulonglong2*>(pW1P + (k4*64 + lane+32)*4);
          const ulonglong2 hv = *reinterpret_cast<const ulonglong2*>(&hs[e][k4*4]);
          pa = ffma2(hv.x, wA.x, pa); pa = ffma2(hv.y, wA.y, pa);
          pb = ffma2(hv.x, wB.x, pb); pb = ffma2(hv.y, wB.y, pb);
        }
        float p_a = fmaxf(hsum2(pa) + pb1[lane],    0.f);
        float p_b = fmaxf(hsum2(pb) + pb1[lane+32], 0.f);
        u64 P01 = warpsum2(pack2(p_a*pW2[lane*3+0] + p_b*pW2[(lane+32)*3+0],
                                 p_a*pW2[lane*3+1] + p_b*pW2[(lane+32)*3+1]));
        float ph2 = warpsum(p_a*pW2[lane*3+2] + p_b*pW2[(lane+32)*3+2]);
        if (lane == 0){
          physs[e][0] = lo2(P01) + pb2[0];
          physs[e][1] = hi2(P01) + pb2[1];
          physs[e][2] = ph2      + pb2[2];
        }
      } else {
        u64 aa = 0ull, ab = 0ull;
        #pragma unroll 4
        for (int k4 = 0; k4 < 32; k4++){
          const ulonglong2 wA = *reinterpret_cast<const ulonglong2*>(aW1P + (k4*64 + lane   )*4);
          const ulonglong2 wB = *reinterpret_cast<const ulonglong2*>(aW1P + (k4*64 + lane+32)*4);
          const ulonglong2 hv = *reinterpret_cast<const ulonglong2*>(&hs[e][k4*4]);
          aa = ffma2(hv.x, wA.x, aa); aa = ffma2(hv.y, wA.y, aa);
          ab = ffma2(hv.x, wB.x, ab); ab = ffma2(hv.y, wB.y, ab);
        }
        scr[e][lane]    = fmaxf(hsum2(aa) + ab1[lane],    0.f);
        scr[e][lane+32] = fmaxf(hsum2(ab) + ab1[lane+32], 0.f);
        __syncwarp();
        u64 t2a = 0ull;
        #pragma unroll
        for (int k4 = 0; k4 < 16; k4++){
          const ulonglong2 wv = *reinterpret_cast<const ulonglong2*>(aW2P + (k4*32 + lane)*4);
          const ulonglong2 sv = *reinterpret_cast<const ulonglong2*>(&scr[e][k4*4]);
          t2a = ffma2(sv.x, wv.x, t2a); t2a = ffma2(sv.y, wv.y, t2a);
        }
        t2 = fmaxf(hsum2(t2a) + ab2[lane], 0.f);
      }
      BAR_ELEM(e);

      if (wh == 1){
        u64 A01 = warpsum2(pack2(t2*aW3[lane*3+0], t2*aW3[lane*3+1]));
        float a2 = warpsum(t2*aW3[lane*3+2]);
        if (bRaw < 1024 && lane < 3){
          float v = (lane == 0) ? (lo2(A01) + ab3[0] + 0.1f*physs[e][0])
                  : (lane == 1) ? (hi2(A01) + ab3[1] + 0.1f*physs[e][1])
                                : (a2       + ab3[2] + 0.1f*physs[e][2]);
          out[(b*T_STEPS + t)*3 + lane] = v;
        }
      }
      // trailing barrier elided: physs WAR covered by LN-exchange BAR next step,
      // xs/gates ordered by block-wide __syncthreads.
    }
  }
}

extern "C" void kernel_launch(void* const* d_in, const int* in_sizes, int n_in,
                              void* d_out, int out_size)
{
  const int off = (n_in >= 30) ? 1 : 0;
  const int*   gesture_idx  = (const int*)  d_in[0];
  const float* demographics = (const float*)d_in[1];
  const float* emb_table = (const float*)d_in[2 + off];
  const float* dW1  = (const float*)d_in[3 + off];
  const float* db1  = (const float*)d_in[4 + off];
  const float* dW2  = (const float*)d_in[5 + off];
  const float* db2  = (const float*)d_in[6 + off];
  const float* jiW  = (const float*)d_in[7 + off];
  const float* jib  = (const float*)d_in[8 + off];
  const float* gatW = (const float*)d_in[9 + off];
  const float* gat_asrc = (const float*)d_in[10 + off];
  const float* gat_adst = (const float*)d_in[11 + off];
  const float* gat_b    = (const float*)d_in[12 + off];
  const float* ln_g = (const float*)d_in[13 + off];
  const float* ln_b = (const float*)d_in[14 + off];
  const float* W_ih = (const float*)d_in[15 + off];
  const float* W_hh = (const float*)d_in[16 + off];
  const float* b_ih = (const float*)d_in[17 + off];
  const float* b_hh = (const float*)d_in[18 + off];
  const float* pW1  = (const float*)d_in[19 + off];
  const float* pb1  = (const float*)d_in[20 + off];
  const float* pW2  = (const float*)d_in[21 + off];
  const float* pb2  = (const float*)d_in[22 + off];
  const float* aW1  = (const float*)d_in[23 + off];
  const float* ab1  = (const float*)d_in[24 + off];
  const float* aW2  = (const float*)d_in[25 + off];
  const float* ab2  = (const float*)d_in[26 + off];
  const float* aW3  = (const float*)d_in[27 + off];
  const float* ab3  = (const float*)d_in[28 + off];

  repack_kernel<<<128, 256>>>(gatW, W_ih, W_hh, pW1, aW1, aW2, b_ih, b_hh);
  vkc_kernel<<<296, 256>>>(gesture_idx, demographics, emb_table,
                           dW1, db1, dW2, db2, jiW, jib,
                           gat_asrc, gat_adst, gat_b, ln_g, ln_b,
                           pb1, pW2, pb2,
                           ab1, ab2,
                           aW3, ab3,
                           (float*)d_out);
}